// round 1
// baseline (speedup 1.0000x reference)
#include <cuda_runtime.h>
#include <cuda_bf16.h>
#include <cstdint>

// Problem constants
#define BATCH 4
#define SEQ   2048
#define DM    768
#define NH    12
#define DK    64
#define TOK   (BATCH*SEQ)          // 8192

// Scratch (device globals: no allocation allowed)
__device__ float g_Q[(size_t)BATCH*NH*SEQ*DK];   // [b,h,s,k]
__device__ float g_K[(size_t)BATCH*NH*SEQ*DK];
__device__ float g_V[(size_t)BATCH*NH*SEQ*DK];
__device__ float g_MH[(size_t)TOK*DM];           // [t, h*64+v]

// ---------------------------------------------------------------------------
// Projection GEMM: Out[b,h,s,k] = sum_m X[t,m] * W[h,m,k]
// grid: (TOK/64, NH), block 256 (16x16), 4x4 microtile, BK=16
// ---------------------------------------------------------------------------
__global__ __launch_bounds__(256) void proj_kernel(
    const float* __restrict__ X,   // [TOK, DM]
    const float* __restrict__ W,   // [NH, DM, DK]
    float* __restrict__ Out)       // [B, NH, SEQ, DK]
{
    const int h  = blockIdx.y;
    const int t0 = blockIdx.x * 64;
    const int tid = threadIdx.x;
    const int tx = tid & 15, ty = tid >> 4;

    __shared__ float Xs[16][65];   // [kk][row]
    __shared__ float Ws[16][65];   // [kk][col]

    float acc[4][4] = {};
    const float* Wh = W + (size_t)h * DM * DK;

    for (int m0 = 0; m0 < DM; m0 += 16) {
        #pragma unroll
        for (int i = 0; i < 4; i++) {
            int idx = tid + i * 256;          // 0..1023
            int r = idx >> 4, kk = idx & 15;
            Xs[kk][r] = X[(size_t)(t0 + r) * DM + m0 + kk];
        }
        #pragma unroll
        for (int i = 0; i < 4; i++) {
            int idx = tid + i * 256;
            int kk = idx >> 6, c = idx & 63;
            Ws[kk][c] = Wh[(size_t)(m0 + kk) * DK + c];
        }
        __syncthreads();
        #pragma unroll
        for (int kk = 0; kk < 16; kk++) {
            float a[4], b[4];
            #pragma unroll
            for (int i = 0; i < 4; i++) a[i] = Xs[kk][ty * 4 + i];
            #pragma unroll
            for (int j = 0; j < 4; j++) b[j] = Ws[kk][tx * 4 + j];
            #pragma unroll
            for (int i = 0; i < 4; i++)
                #pragma unroll
                for (int j = 0; j < 4; j++) acc[i][j] += a[i] * b[j];
        }
        __syncthreads();
    }
    #pragma unroll
    for (int i = 0; i < 4; i++) {
        int t = t0 + ty * 4 + i;
        int bb = t / SEQ, s = t % SEQ;
        float* o = Out + (((size_t)bb * NH + h) * SEQ + s) * DK + tx * 4;
        #pragma unroll
        for (int j = 0; j < 4; j++) o[j] = acc[i][j];
    }
}

// ---------------------------------------------------------------------------
// Flash-style causal attention: per (b*H+h, q-tile of 64)
// smem: Qs/Ks/Vs 64x64, Ss 64x65, row stats
// ---------------------------------------------------------------------------
#define SS_STRIDE 65
#define ATTN_SMEM ((3*64*64 + 64*SS_STRIDE + 3*64 + 4*64) * sizeof(float))

__global__ __launch_bounds__(256) void attn_kernel(
    const float* __restrict__ Q,
    const float* __restrict__ K,
    const float* __restrict__ V,
    float* __restrict__ MH)
{
    const int p  = blockIdx.y;   // b*NH + h
    const int qt = blockIdx.x;   // q tile index
    const float* Qb = Q + (size_t)p * SEQ * DK;
    const float* Kb = K + (size_t)p * SEQ * DK;
    const float* Vb = V + (size_t)p * SEQ * DK;

    extern __shared__ float sm[];
    float* Qs    = sm;                    // 64*64
    float* Ks    = Qs + 64 * 64;
    float* Vs    = Ks + 64 * 64;
    float* Ss    = Vs + 64 * 64;          // 64*SS_STRIDE
    float* row_m = Ss + 64 * SS_STRIDE;   // 64
    float* row_l = row_m + 64;
    float* row_a = row_l + 64;
    float* red   = row_a + 64;            // 4*64

    const int tid = threadIdx.x;
    const int tx = tid & 15, ty = tid >> 4;

    // Load Q tile
    #pragma unroll
    for (int i = 0; i < 16; i++) {
        int idx = tid + i * 256;
        int r = idx >> 6, c = idx & 63;
        Qs[r * 64 + c] = Qb[(size_t)(qt * 64 + r) * DK + c];
    }
    if (tid < 64) { row_m[tid] = -1e30f; row_l[tid] = 0.f; }
    float acc[4][4] = {};
    __syncthreads();

    const float scale = 0.125f;  // 1/sqrt(64)

    for (int j = 0; j <= qt; j++) {
        // Load K, V tiles
        #pragma unroll
        for (int i = 0; i < 16; i++) {
            int idx = tid + i * 256;
            int r = idx >> 6, c = idx & 63;
            Ks[r * 64 + c] = Kb[(size_t)(j * 64 + r) * DK + c];
            Vs[r * 64 + c] = Vb[(size_t)(j * 64 + r) * DK + c];
        }
        __syncthreads();

        // S = Q K^T (4x4 per thread)
        float sacc[4][4] = {};
        #pragma unroll
        for (int kk = 0; kk < 64; kk++) {
            float a[4], b[4];
            #pragma unroll
            for (int i = 0; i < 4; i++) a[i] = Qs[(ty * 4 + i) * 64 + kk];
            #pragma unroll
            for (int jj = 0; jj < 4; jj++) b[jj] = Ks[(tx * 4 + jj) * 64 + kk];
            #pragma unroll
            for (int i = 0; i < 4; i++)
                #pragma unroll
                for (int jj = 0; jj < 4; jj++) sacc[i][jj] += a[i] * b[jj];
        }
        const bool diag = (j == qt);
        #pragma unroll
        for (int i = 0; i < 4; i++)
            #pragma unroll
            for (int jj = 0; jj < 4; jj++) {
                float v = sacc[i][jj] * scale;
                if (diag && (tx * 4 + jj) > (ty * 4 + i)) v = -1e30f;
                Ss[(ty * 4 + i) * SS_STRIDE + tx * 4 + jj] = v;
            }
        __syncthreads();

        // Row max (4 partials per row)
        {
            int r = tid & 63, part = tid >> 6;
            float mx = -1e30f;
            #pragma unroll
            for (int c = 0; c < 16; c++)
                mx = fmaxf(mx, Ss[r * SS_STRIDE + part * 16 + c]);
            red[part * 64 + r] = mx;
        }
        __syncthreads();
        if (tid < 64) {
            int r = tid;
            float mx = fmaxf(fmaxf(red[r], red[64 + r]), fmaxf(red[128 + r], red[192 + r]));
            float m_new = fmaxf(row_m[r], mx);
            row_a[r] = __expf(row_m[r] - m_new);
            row_m[r] = m_new;
        }
        __syncthreads();

        // exp + partial sums
        {
            int r = tid & 63, part = tid >> 6;
            float m = row_m[r];
            float s = 0.f;
            #pragma unroll
            for (int c = 0; c < 16; c++) {
                float pv = __expf(Ss[r * SS_STRIDE + part * 16 + c] - m);
                Ss[r * SS_STRIDE + part * 16 + c] = pv;
                s += pv;
            }
            red[part * 64 + r] = s;
        }
        __syncthreads();
        if (tid < 64) {
            int r = tid;
            row_l[r] = row_l[r] * row_a[r] + red[r] + red[64 + r] + red[128 + r] + red[192 + r];
        }
        __syncthreads();

        // O += P V, with rescale
        float al[4];
        #pragma unroll
        for (int i = 0; i < 4; i++) al[i] = row_a[ty * 4 + i];
        float pacc[4][4] = {};
        #pragma unroll
        for (int ss = 0; ss < 64; ss++) {
            float a[4], b[4];
            #pragma unroll
            for (int i = 0; i < 4; i++) a[i] = Ss[(ty * 4 + i) * SS_STRIDE + ss];
            #pragma unroll
            for (int jj = 0; jj < 4; jj++) b[jj] = Vs[ss * 64 + tx * 4 + jj];
            #pragma unroll
            for (int i = 0; i < 4; i++)
                #pragma unroll
                for (int jj = 0; jj < 4; jj++) pacc[i][jj] += a[i] * b[jj];
        }
        #pragma unroll
        for (int i = 0; i < 4; i++)
            #pragma unroll
            for (int jj = 0; jj < 4; jj++)
                acc[i][jj] = acc[i][jj] * al[i] + pacc[i][jj];
        __syncthreads();
    }

    // Write out: MH[(b*SEQ+s)*DM + h*64 + c]
    const int b = p / NH, h = p % NH;
    #pragma unroll
    for (int i = 0; i < 4; i++) {
        int s = qt * 64 + ty * 4 + i;
        float inv = 1.f / row_l[ty * 4 + i];
        float* o = MH + ((size_t)(b * SEQ + s)) * DM + h * 64 + tx * 4;
        #pragma unroll
        for (int jj = 0; jj < 4; jj++) o[jj] = acc[i][jj] * inv;
    }
}

// ---------------------------------------------------------------------------
// Output projection: Out[t,d] = sum_n MH[t,n] * W_O[n,d]
// grid: (TOK/64, DM/64)
// ---------------------------------------------------------------------------
__global__ __launch_bounds__(256) void oproj_kernel(
    const float* __restrict__ MHp,   // [TOK, DM]
    const float* __restrict__ WO,    // [DM, DM]  (n, d)
    float* __restrict__ Out)         // [TOK, DM]
{
    const int d0 = blockIdx.y * 64;
    const int t0 = blockIdx.x * 64;
    const int tid = threadIdx.x;
    const int tx = tid & 15, ty = tid >> 4;

    __shared__ float As[16][65];
    __shared__ float Bs[16][65];

    float acc[4][4] = {};

    for (int m0 = 0; m0 < DM; m0 += 16) {
        #pragma unroll
        for (int i = 0; i < 4; i++) {
            int idx = tid + i * 256;
            int r = idx >> 4, kk = idx & 15;
            As[kk][r] = MHp[(size_t)(t0 + r) * DM + m0 + kk];
        }
        #pragma unroll
        for (int i = 0; i < 4; i++) {
            int idx = tid + i * 256;
            int kk = idx >> 6, c = idx & 63;
            Bs[kk][c] = WO[(size_t)(m0 + kk) * DM + d0 + c];
        }
        __syncthreads();
        #pragma unroll
        for (int kk = 0; kk < 16; kk++) {
            float a[4], b[4];
            #pragma unroll
            for (int i = 0; i < 4; i++) a[i] = As[kk][ty * 4 + i];
            #pragma unroll
            for (int j = 0; j < 4; j++) b[j] = Bs[kk][tx * 4 + j];
            #pragma unroll
            for (int i = 0; i < 4; i++)
                #pragma unroll
                for (int j = 0; j < 4; j++) acc[i][j] += a[i] * b[j];
        }
        __syncthreads();
    }
    #pragma unroll
    for (int i = 0; i < 4; i++) {
        float* o = Out + (size_t)(t0 + ty * 4 + i) * DM + d0 + tx * 4;
        #pragma unroll
        for (int j = 0; j < 4; j++) o[j] = acc[i][j];
    }
}

// ---------------------------------------------------------------------------
extern "C" void kernel_launch(void* const* d_in, const int* in_sizes, int n_in,
                              void* d_out, int out_size)
{
    const float* residual = (const float*)d_in[0];  // [B,S,DM]
    const float* W_Q = (const float*)d_in[1];       // [H,DM,DK]
    const float* W_K = (const float*)d_in[2];
    const float* W_V = (const float*)d_in[3];
    const float* W_O = (const float*)d_in[4];       // [H*DV, DM]
    float* out = (float*)d_out;                     // [B,S,DM]

    float *qp, *kp, *vp, *mhp;
    cudaGetSymbolAddress((void**)&qp,  g_Q);
    cudaGetSymbolAddress((void**)&kp,  g_K);
    cudaGetSymbolAddress((void**)&vp,  g_V);
    cudaGetSymbolAddress((void**)&mhp, g_MH);

    cudaFuncSetAttribute(attn_kernel, cudaFuncAttributeMaxDynamicSharedMemorySize,
                         (int)ATTN_SMEM);

    dim3 gproj(TOK / 64, NH);
    proj_kernel<<<gproj, 256>>>(residual, W_Q, qp);
    proj_kernel<<<gproj, 256>>>(residual, W_K, kp);
    proj_kernel<<<gproj, 256>>>(residual, W_V, vp);

    dim3 gattn(SEQ / 64, BATCH * NH);
    attn_kernel<<<gattn, 256, ATTN_SMEM>>>(qp, kp, vp, mhp);

    dim3 goproj(TOK / 64, DM / 64);
    oproj_kernel<<<goproj, 256>>>(mhp, W_O, out);
}

// round 4
// speedup vs baseline: 3.6951x; 3.6951x over previous
#include <cuda_runtime.h>
#include <cuda_bf16.h>
#include <cstdint>

#define BATCH 4
#define SEQ   2048
#define DM    768
#define NH    12
#define TOK   (BATCH*SEQ)   // 8192

// ---------------------------------------------------------------------------
// Scratch (uint4 for guaranteed 16B alignment; cast as needed)
// ---------------------------------------------------------------------------
__device__ uint4 g_Xhi4 [(size_t)TOK*DM/8],  g_Xlo4 [(size_t)TOK*DM/8];
__device__ uint4 g_Wthi4[(size_t)3*NH*64*DM/8], g_Wtlo4[(size_t)3*NH*64*DM/8]; // [mat*NH+h][n][m]
__device__ uint4 g_WOthi4[(size_t)DM*DM/8], g_WOtlo4[(size_t)DM*DM/8];         // [d][n]
__device__ uint4 g_Qhi4 [(size_t)TOK*DM/8], g_Qlo4 [(size_t)TOK*DM/8];  // [b,h,s,d]
__device__ uint4 g_Khi4 [(size_t)TOK*DM/8], g_Klo4 [(size_t)TOK*DM/8];  // [b,h,s,d]
__device__ uint4 g_Vthi4[(size_t)TOK*DM/8], g_Vtlo4[(size_t)TOK*DM/8];  // [b,h,d,s]
__device__ uint4 g_MHhi4[(size_t)TOK*DM/8], g_MHlo4[(size_t)TOK*DM/8];  // [t, h*64+v]

#define BF(p) ((__nv_bfloat16*)(p))

// ---------------------------------------------------------------------------
// Helpers
// ---------------------------------------------------------------------------
__device__ __forceinline__ void mma_bf16(float* d, uint32_t a0, uint32_t a1,
                                         uint32_t a2, uint32_t a3,
                                         uint32_t b0, uint32_t b1){
    asm volatile("mma.sync.aligned.m16n8k16.row.col.f32.bf16.bf16.f32 "
        "{%0,%1,%2,%3}, {%4,%5,%6,%7}, {%8,%9}, {%0,%1,%2,%3};"
        : "+f"(d[0]), "+f"(d[1]), "+f"(d[2]), "+f"(d[3])
        : "r"(a0), "r"(a1), "r"(a2), "r"(a3), "r"(b0), "r"(b1));
}

// A fragment from row-major smem (stride in halfwords), base already at (row, k0+c2)
__device__ __forceinline__ void lda(const ushort* base, int stride, uint32_t* a){
    a[0] = *(const uint32_t*)(base);
    a[1] = *(const uint32_t*)(base + 8*stride);
    a[2] = *(const uint32_t*)(base + 8);
    a[3] = *(const uint32_t*)(base + 8*stride + 8);
}

__device__ __forceinline__ void pack_hilo(float v0, float v1, uint32_t& hi, uint32_t& lo){
    __nv_bfloat162 hp = __floats2bfloat162_rn(v0, v1);
    float l0 = v0 - __bfloat162float(hp.x);
    float l1 = v1 - __bfloat162float(hp.y);
    __nv_bfloat162 lp = __floats2bfloat162_rn(l0, l1);
    hi = *(uint32_t*)&hp; lo = *(uint32_t*)&lp;
}

__device__ __forceinline__ void st8h(ushort* sh, int hoff, uint4 v){
    uint32_t* p = (uint32_t*)(sh + hoff);
    p[0] = v.x; p[1] = v.y; p[2] = v.z; p[3] = v.w;
}

__device__ __forceinline__ float exp2_fast(float t){
    t = fmaxf(t, -126.f);
    float fi = floorf(t);
    float f = t - fi;
    float p = 1.5403530e-4f;
    p = fmaf(p, f, 1.3333558e-3f);
    p = fmaf(p, f, 9.6181291e-3f);
    p = fmaf(p, f, 5.5504109e-2f);
    p = fmaf(p, f, 2.4022651e-1f);
    p = fmaf(p, f, 6.9314718e-1f);
    p = fmaf(p, f, 1.0f);
    return p * __int_as_float(((int)fi + 127) << 23);
}

// ---------------------------------------------------------------------------
// Prep: fp32 -> bf16 hi/lo (+ weight transposes)
// ---------------------------------------------------------------------------
__global__ __launch_bounds__(256) void prep_x(const float* __restrict__ X){
    int i0 = (blockIdx.x * 256 + threadIdx.x) * 8;
    #pragma unroll
    for (int k = 0; k < 8; k++){
        int i = i0 + k;
        float v = X[i];
        __nv_bfloat16 h = __float2bfloat16(v);
        BF(g_Xhi4)[i] = h;
        BF(g_Xlo4)[i] = __float2bfloat16(v - __bfloat162float(h));
    }
}

__global__ __launch_bounds__(256) void prep_wqkv(const float* __restrict__ WQ,
                                                 const float* __restrict__ WK,
                                                 const float* __restrict__ WV){
    __shared__ float tile[64][65];
    int x = blockIdx.x;               // mat*12 + h
    int mt = blockIdx.y;              // m tile (12)
    int mat = x / NH, h = x % NH;
    const float* src = (mat == 0 ? WQ : mat == 1 ? WK : WV) + (size_t)h * DM * 64;
    int tid = threadIdx.x;
    #pragma unroll
    for (int i = 0; i < 16; i++){
        int idx = tid + i * 256;
        int r = idx >> 6, c = idx & 63;
        tile[r][c] = src[(size_t)(mt * 64 + r) * 64 + c];
    }
    __syncthreads();
    #pragma unroll
    for (int i = 0; i < 16; i++){
        int idx = tid + i * 256;
        int n = idx >> 6, mc = idx & 63;
        float v = tile[mc][n];
        __nv_bfloat16 hh = __float2bfloat16(v);
        size_t o = ((size_t)x * 64 + n) * DM + mt * 64 + mc;
        BF(g_Wthi4)[o] = hh;
        BF(g_Wtlo4)[o] = __float2bfloat16(v - __bfloat162float(hh));
    }
}

__global__ __launch_bounds__(256) void prep_wo(const float* __restrict__ WO){
    __shared__ float tile[64][65];
    int nt = blockIdx.x, dt = blockIdx.y;
    int tid = threadIdx.x;
    #pragma unroll
    for (int i = 0; i < 16; i++){
        int idx = tid + i * 256;
        int r = idx >> 6, c = idx & 63;
        tile[r][c] = WO[(size_t)(nt * 64 + r) * DM + dt * 64 + c];
    }
    __syncthreads();
    #pragma unroll
    for (int i = 0; i < 16; i++){
        int idx = tid + i * 256;
        int dr = idx >> 6, nc = idx & 63;
        float v = tile[nc][dr];
        __nv_bfloat16 hh = __float2bfloat16(v);
        size_t o = (size_t)(dt * 64 + dr) * DM + nt * 64 + nc;
        BF(g_WOthi4)[o] = hh;
        BF(g_WOtlo4)[o] = __float2bfloat16(v - __bfloat162float(hh));
    }
}

// ---------------------------------------------------------------------------
// GEMM mainloop: 128x128 tile, K chunks of 32, 8 warps (4m x 2n)
// smem stride 36 halfwords. acc[2][8][4].
// ---------------------------------------------------------------------------
#define GEMM_SA 36

__device__ __forceinline__ void gemm_mainloop(
    const uint4* __restrict__ GAH, const uint4* __restrict__ GAL,
    const uint4* __restrict__ GBH, const uint4* __restrict__ GBL,
    int arow0, int brow0,
    ushort* sAh, ushort* sAl, ushort* sBh, ushort* sBl,
    int tid, int wm, int wn, int r, int c2,
    float acc[2][8][4])
{
    for (int ch = 0; ch < 24; ch++){
        {
            int lrow = tid >> 1, lh = tid & 1;
            size_t ai = (size_t)(arow0 + lrow) * 96 + ch * 4 + lh * 2;
            size_t bi = (size_t)(brow0 + lrow) * 96 + ch * 4 + lh * 2;
            int so = lrow * GEMM_SA + lh * 16;
            uint4 v;
            v = GAH[ai];     st8h(sAh, so, v);
            v = GAH[ai + 1]; st8h(sAh, so + 8, v);
            v = GAL[ai];     st8h(sAl, so, v);
            v = GAL[ai + 1]; st8h(sAl, so + 8, v);
            v = GBH[bi];     st8h(sBh, so, v);
            v = GBH[bi + 1]; st8h(sBh, so + 8, v);
            v = GBL[bi];     st8h(sBl, so, v);
            v = GBL[bi + 1]; st8h(sBl, so + 8, v);
        }
        __syncthreads();
        #pragma unroll
        for (int k0 = 0; k0 < 32; k0 += 16){
            uint32_t ah[2][4], al[2][4];
            #pragma unroll
            for (int mt = 0; mt < 2; mt++){
                int ro = (wm * 32 + mt * 16 + r) * GEMM_SA + k0 + c2;
                lda(sAh + ro, GEMM_SA, ah[mt]);
                lda(sAl + ro, GEMM_SA, al[mt]);
            }
            #pragma unroll
            for (int nt = 0; nt < 8; nt++){
                int bo = (wn * 64 + nt * 8 + r) * GEMM_SA + k0 + c2;
                uint32_t bh0 = *(const uint32_t*)(sBh + bo);
                uint32_t bh1 = *(const uint32_t*)(sBh + bo + 8);
                uint32_t bl0 = *(const uint32_t*)(sBl + bo);
                uint32_t bl1 = *(const uint32_t*)(sBl + bo + 8);
                #pragma unroll
                for (int mt = 0; mt < 2; mt++){
                    mma_bf16(acc[mt][nt], ah[mt][0], ah[mt][1], ah[mt][2], ah[mt][3], bh0, bh1);
                    mma_bf16(acc[mt][nt], ah[mt][0], ah[mt][1], ah[mt][2], ah[mt][3], bl0, bl1);
                    mma_bf16(acc[mt][nt], al[mt][0], al[mt][1], al[mt][2], al[mt][3], bh0, bh1);
                }
            }
        }
        __syncthreads();
    }
}

// QKV projection: A = X[t, m], B = Wt[(mat*NH+h0..+1)*64 + n][m]
__global__ __launch_bounds__(256) void gemm_qkv(){
    __shared__ __align__(16) ushort sAh[128*GEMM_SA], sAl[128*GEMM_SA];
    __shared__ __align__(16) ushort sBh[128*GEMM_SA], sBl[128*GEMM_SA];
    const int tid = threadIdx.x, w = tid >> 5, lane = tid & 31;
    const int wm = w & 3, wn = w >> 2;
    const int r = lane >> 2, c2 = (lane & 3) * 2;
    const int t0 = blockIdx.x * 128;
    const int j = blockIdx.y;
    const int mat = j / 6, h0 = (j % 6) * 2;
    const int brow0 = (mat * NH + h0) * 64;

    float acc[2][8][4] = {};
    gemm_mainloop(g_Xhi4, g_Xlo4, g_Wthi4, g_Wtlo4, t0, brow0,
                  sAh, sAl, sBh, sBl, tid, wm, wn, r, c2, acc);

    const int hh_g = h0 + wn;
    #pragma unroll
    for (int mt = 0; mt < 2; mt++){
        #pragma unroll
        for (int hf = 0; hf < 2; hf++){
            int srow = t0 + wm * 32 + mt * 16 + r + hf * 8;
            int bb = srow >> 11, s = srow & 2047;
            if (mat < 2){
                uint32_t* DH = (uint32_t*)(mat == 0 ? g_Qhi4 : g_Khi4);
                uint32_t* DL = (uint32_t*)(mat == 0 ? g_Qlo4 : g_Klo4);
                size_t base = ((size_t)(bb * NH + hh_g) * SEQ + s) * 32;
                #pragma unroll
                for (int nt = 0; nt < 8; nt++){
                    int d = nt * 8 + c2;
                    uint32_t hi, lo;
                    pack_hilo(acc[mt][nt][hf*2], acc[mt][nt][hf*2+1], hi, lo);
                    DH[base + (d >> 1)] = hi;
                    DL[base + (d >> 1)] = lo;
                }
            } else {
                __nv_bfloat16* VH = BF(g_Vthi4);
                __nv_bfloat16* VL = BF(g_Vtlo4);
                #pragma unroll
                for (int nt = 0; nt < 8; nt++){
                    #pragma unroll
                    for (int j2 = 0; j2 < 2; j2++){
                        int d = nt * 8 + c2 + j2;
                        float v = acc[mt][nt][hf*2+j2];
                        __nv_bfloat16 hb = __float2bfloat16(v);
                        size_t o = ((size_t)(bb * NH + hh_g) * 64 + d) * SEQ + s;
                        VH[o] = hb;
                        VL[o] = __float2bfloat16(v - __bfloat162float(hb));
                    }
                }
            }
        }
    }
}

// Output projection: A = MH[t, n], B = WOt[d][n], C = out[t, d] (fp32)
__global__ __launch_bounds__(256) void gemm_oproj(float* __restrict__ out){
    __shared__ __align__(16) ushort sAh[128*GEMM_SA], sAl[128*GEMM_SA];
    __shared__ __align__(16) ushort sBh[128*GEMM_SA], sBl[128*GEMM_SA];
    const int tid = threadIdx.x, w = tid >> 5, lane = tid & 31;
    const int wm = w & 3, wn = w >> 2;
    const int r = lane >> 2, c2 = (lane & 3) * 2;
    const int t0 = blockIdx.x * 128;
    const int d0 = blockIdx.y * 128;

    float acc[2][8][4] = {};
    gemm_mainloop(g_MHhi4, g_MHlo4, g_WOthi4, g_WOtlo4, t0, d0,
                  sAh, sAl, sBh, sBl, tid, wm, wn, r, c2, acc);

    #pragma unroll
    for (int mt = 0; mt < 2; mt++){
        #pragma unroll
        for (int hf = 0; hf < 2; hf++){
            int srow = t0 + wm * 32 + mt * 16 + r + hf * 8;
            #pragma unroll
            for (int nt = 0; nt < 8; nt++){
                int dcol = d0 + wn * 64 + nt * 8 + c2;
                float2 v = make_float2(acc[mt][nt][hf*2], acc[mt][nt][hf*2+1]);
                *(float2*)(out + (size_t)srow * DM + dcol) = v;
            }
        }
    }
}

// ---------------------------------------------------------------------------
// Flash attention (mma.sync): 128-q tile, 64-kv tile, 8 warps (4m x 2n)
// smem (halfword offsets, stride 72):
//   Qh 0, Ql 9216 | K/P union: Kh 18432, Kl 23040; Ph 18432, Pl 27648
//   Vh 36864, Vl 41472 | stats (floats) at byte 92160
// ---------------------------------------------------------------------------
#define ASA   72
#define AQ_H  0
#define AQ_L  9216
#define AK_H  18432
#define AK_L  23040
#define AP_H  18432
#define AP_L  27648
#define AV_H  36864
#define AV_L  41472
#define ASTAT 92160
#define ATTN_SMEM (ASTAT + 6*128*4)   // 95232

__global__ __launch_bounds__(256) void attn_kernel(){
    extern __shared__ __align__(16) char smem[];
    ushort* sh    = (ushort*)smem;
    float* sm_m   = (float*)(smem + ASTAT);
    float* sm_l   = sm_m + 128;
    float* redmax = sm_l + 128;     // [2][128]
    float* redsum = redmax + 256;   // [2][128]

    const int tid = threadIdx.x, w = tid >> 5, lane = tid & 31;
    const int wm = w & 3, wn = w >> 2;
    const int r = lane >> 2, c2 = (lane & 3) * 2;

    const int qt = 15 - blockIdx.x;   // heavy tiles first
    const int pr = blockIdx.y;
    const int b = pr / NH, h = pr % NH;

    // Load Q tile (128 x 64 half, hi+lo)
    {
        const uint4* QH = g_Qhi4 + ((size_t)(b * NH + h) * SEQ + qt * 128) * 8;
        const uint4* QL = g_Qlo4 + ((size_t)(b * NH + h) * SEQ + qt * 128) * 8;
        int lrow = tid >> 1, lh = tid & 1;
        size_t gi = (size_t)lrow * 8 + lh * 4;
        int so = lrow * ASA + lh * 32;
        #pragma unroll
        for (int i = 0; i < 4; i++){
            st8h(sh + AQ_H, so + i * 8, QH[gi + i]);
            st8h(sh + AQ_L, so + i * 8, QL[gi + i]);
        }
    }
    if (tid < 128){ sm_m[tid] = -1e30f; sm_l[tid] = 0.f; }

    float O[2][4][4] = {};
    const float CSC = 0.125f * 1.4426950408889634f;  // scale * log2(e)
    const int jmax = 2 * qt + 1;

    for (int jj = 0; jj <= jmax; jj++){
        // Load K (s-major) and V^T (d-major) tiles, hi+lo: 64 x 64 half each
        {
            const uint4* KH = g_Khi4  + ((size_t)(b * NH + h) * SEQ + jj * 64) * 8;
            const uint4* KL = g_Klo4  + ((size_t)(b * NH + h) * SEQ + jj * 64) * 8;
            const uint4* VH = g_Vthi4 + ((size_t)(b * NH + h) * 64) * (SEQ / 8);
            const uint4* VL = g_Vtlo4 + ((size_t)(b * NH + h) * 64) * (SEQ / 8);
            int lrow = tid >> 2, lq = tid & 3;
            size_t ki = (size_t)lrow * 8 + lq * 2;
            size_t vi = (size_t)lrow * (SEQ / 8) + jj * 8 + lq * 2;
            int so = lrow * ASA + lq * 16;
            uint4 v;
            v = KH[ki];     st8h(sh + AK_H, so, v);
            v = KH[ki + 1]; st8h(sh + AK_H, so + 8, v);
            v = KL[ki];     st8h(sh + AK_L, so, v);
            v = KL[ki + 1]; st8h(sh + AK_L, so + 8, v);
            v = VH[vi];     st8h(sh + AV_H, so, v);
            v = VH[vi + 1]; st8h(sh + AV_H, so + 8, v);
            v = VL[vi];     st8h(sh + AV_L, so, v);
            v = VL[vi + 1]; st8h(sh + AV_L, so + 8, v);
        }
        __syncthreads();

        // ---- S = Q K^T (3-term compensated) ----
        float sacc[2][4][4] = {};
        #pragma unroll
        for (int k0 = 0; k0 < 64; k0 += 16){
            uint32_t ah[2][4], al[2][4];
            #pragma unroll
            for (int mt = 0; mt < 2; mt++){
                int ro = (wm * 32 + mt * 16 + r) * ASA + k0 + c2;
                lda(sh + AQ_H + ro, ASA, ah[mt]);
                lda(sh + AQ_L + ro, ASA, al[mt]);
            }
            #pragma unroll
            for (int nt = 0; nt < 4; nt++){
                int bo = (wn * 32 + nt * 8 + r) * ASA + k0 + c2;
                uint32_t bh0 = *(const uint32_t*)(sh + AK_H + bo);
                uint32_t bh1 = *(const uint32_t*)(sh + AK_H + bo + 8);
                uint32_t bl0 = *(const uint32_t*)(sh + AK_L + bo);
                uint32_t bl1 = *(const uint32_t*)(sh + AK_L + bo + 8);
                #pragma unroll
                for (int mt = 0; mt < 2; mt++){
                    mma_bf16(sacc[mt][nt], ah[mt][0], ah[mt][1], ah[mt][2], ah[mt][3], bh0, bh1);
                    mma_bf16(sacc[mt][nt], ah[mt][0], ah[mt][1], ah[mt][2], ah[mt][3], bl0, bl1);
                    mma_bf16(sacc[mt][nt], al[mt][0], al[mt][1], al[mt][2], al[mt][3], bh0, bh1);
                }
            }
        }

        // ---- scale + causal mask + local row max ----
        #pragma unroll
        for (int mt = 0; mt < 2; mt++){
            #pragma unroll
            for (int hf = 0; hf < 2; hf++){
                int qrow = qt * 128 + wm * 32 + mt * 16 + r + hf * 8;
                float mx = -1e30f;
                #pragma unroll
                for (int nt = 0; nt < 4; nt++){
                    #pragma unroll
                    for (int j2 = 0; j2 < 2; j2++){
                        int col = jj * 64 + wn * 32 + nt * 8 + c2 + j2;
                        float v = sacc[mt][nt][hf*2+j2] * CSC;
                        if (col > qrow) v = -1e30f;
                        sacc[mt][nt][hf*2+j2] = v;
                        mx = fmaxf(mx, v);
                    }
                }
                mx = fmaxf(mx, __shfl_xor_sync(0xffffffffu, mx, 1));
                mx = fmaxf(mx, __shfl_xor_sync(0xffffffffu, mx, 2));
                if ((lane & 3) == 0)
                    redmax[wn * 128 + wm * 32 + mt * 16 + r + hf * 8] = mx;
            }
        }
        __syncthreads();   // (A) redmax ready; K region free

        // ---- m_new, alpha, exp, sums; write P to smem (over K region) ----
        float alpha[2][2], mnew[2][2];
        #pragma unroll
        for (int mt = 0; mt < 2; mt++){
            #pragma unroll
            for (int hf = 0; hf < 2; hf++){
                int row = wm * 32 + mt * 16 + r + hf * 8;
                float mo = sm_m[row];
                float mn = fmaxf(mo, fmaxf(redmax[row], redmax[128 + row]));
                mnew[mt][hf] = mn;
                alpha[mt][hf] = exp2_fast(mo - mn);
                float rs = 0.f;
                #pragma unroll
                for (int nt = 0; nt < 4; nt++){
                    #pragma unroll
                    for (int j2 = 0; j2 < 2; j2++){
                        float p = exp2_fast(sacc[mt][nt][hf*2+j2] - mn);
                        sacc[mt][nt][hf*2+j2] = p;
                        rs += p;
                    }
                }
                rs += __shfl_xor_sync(0xffffffffu, rs, 1);
                rs += __shfl_xor_sync(0xffffffffu, rs, 2);
                if ((lane & 3) == 0)
                    redsum[wn * 128 + row] = rs;
                // write P hi/lo pairs
                #pragma unroll
                for (int nt = 0; nt < 4; nt++){
                    uint32_t hi, lo;
                    pack_hilo(sacc[mt][nt][hf*2], sacc[mt][nt][hf*2+1], hi, lo);
                    int po = row * ASA + wn * 32 + nt * 8 + c2;
                    *(uint32_t*)(sh + AP_H + po) = hi;
                    *(uint32_t*)(sh + AP_L + po) = lo;
                }
            }
        }
        __syncthreads();   // (B) redsum + P visible

        // stats update (one owner per row)
        if (wn == 0 && (lane & 3) == 0){
            #pragma unroll
            for (int mt = 0; mt < 2; mt++){
                #pragma unroll
                for (int hf = 0; hf < 2; hf++){
                    int row = wm * 32 + mt * 16 + r + hf * 8;
                    sm_l[row] = sm_l[row] * alpha[mt][hf] + redsum[row] + redsum[128 + row];
                    sm_m[row] = mnew[mt][hf];
                }
            }
        }

        // ---- O rescale + PV (3-term) ----
        #pragma unroll
        for (int mt = 0; mt < 2; mt++)
            #pragma unroll
            for (int nt = 0; nt < 4; nt++){
                O[mt][nt][0] *= alpha[mt][0];
                O[mt][nt][1] *= alpha[mt][0];
                O[mt][nt][2] *= alpha[mt][1];
                O[mt][nt][3] *= alpha[mt][1];
            }
        #pragma unroll
        for (int k0 = 0; k0 < 64; k0 += 16){
            uint32_t ah[2][4], al[2][4];
            #pragma unroll
            for (int mt = 0; mt < 2; mt++){
                int ro = (wm * 32 + mt * 16 + r) * ASA + k0 + c2;
                lda(sh + AP_H + ro, ASA, ah[mt]);
                lda(sh + AP_L + ro, ASA, al[mt]);
            }
            #pragma unroll
            for (int nt = 0; nt < 4; nt++){
                int bo = (wn * 32 + nt * 8 + r) * ASA + k0 + c2;
                uint32_t bh0 = *(const uint32_t*)(sh + AV_H + bo);
                uint32_t bh1 = *(const uint32_t*)(sh + AV_H + bo + 8);
                uint32_t bl0 = *(const uint32_t*)(sh + AV_L + bo);
                uint32_t bl1 = *(const uint32_t*)(sh + AV_L + bo + 8);
                #pragma unroll
                for (int mt = 0; mt < 2; mt++){
                    mma_bf16(O[mt][nt], ah[mt][0], ah[mt][1], ah[mt][2], ah[mt][3], bh0, bh1);
                    mma_bf16(O[mt][nt], ah[mt][0], ah[mt][1], ah[mt][2], ah[mt][3], bl0, bl1);
                    mma_bf16(O[mt][nt], al[mt][0], al[mt][1], al[mt][2], al[mt][3], bh0, bh1);
                }
            }
        }
        __syncthreads();   // (C) P/V consumed; stats final
    }

    // ---- write MH hi/lo ----
    uint32_t* MHH = (uint32_t*)g_MHhi4;
    uint32_t* MHL = (uint32_t*)g_MHlo4;
    #pragma unroll
    for (int mt = 0; mt < 2; mt++){
        #pragma unroll
        for (int hf = 0; hf < 2; hf++){
            int row = wm * 32 + mt * 16 + r + hf * 8;
            float linv = 1.f / sm_l[row];
            size_t t = (size_t)b * SEQ + qt * 128 + row;
            #pragma unroll
            for (int nt = 0; nt < 4; nt++){
                int col = h * 64 + wn * 32 + nt * 8 + c2;
                uint32_t hi, lo;
                pack_hilo(O[mt][nt][hf*2] * linv, O[mt][nt][hf*2+1] * linv, hi, lo);
                MHH[(t * DM + col) >> 1] = hi;
                MHL[(t * DM + col) >> 1] = lo;
            }
        }
    }
}

// ---------------------------------------------------------------------------
extern "C" void kernel_launch(void* const* d_in, const int* in_sizes, int n_in,
                              void* d_out, int out_size)
{
    const float* residual = (const float*)d_in[0];
    const float* W_Q = (const float*)d_in[1];
    const float* W_K = (const float*)d_in[2];
    const float* W_V = (const float*)d_in[3];
    const float* W_O = (const float*)d_in[4];
    float* out = (float*)d_out;

    cudaFuncSetAttribute(attn_kernel, cudaFuncAttributeMaxDynamicSharedMemorySize, ATTN_SMEM);

    prep_x<<<TOK * DM / (256 * 8), 256>>>(residual);
    prep_wqkv<<<dim3(3 * NH, 12), 256>>>(W_Q, W_K, W_V);
    prep_wo<<<dim3(12, 12), 256>>>(W_O);

    gemm_qkv<<<dim3(64, 18), 256>>>();
    attn_kernel<<<dim3(16, BATCH * NH), 256, ATTN_SMEM>>>();
    gemm_oproj<<<dim3(64, 6), 256>>>(out);
}

// round 5
// speedup vs baseline: 4.3110x; 1.1667x over previous
#include <cuda_runtime.h>
#include <cuda_bf16.h>
#include <cstdint>

#define BATCH 4
#define SEQ   2048
#define DM    768
#define NH    12
#define TOK   (BATCH*SEQ)   // 8192

// ---------------------------------------------------------------------------
// Scratch (uint4 for guaranteed 16B alignment; cast as needed)
// ---------------------------------------------------------------------------
__device__ uint4 g_Xhi4 [(size_t)TOK*DM/8],  g_Xlo4 [(size_t)TOK*DM/8];
__device__ uint4 g_Wthi4[(size_t)3*NH*64*DM/8], g_Wtlo4[(size_t)3*NH*64*DM/8]; // [mat*NH+h][n][m]
__device__ uint4 g_WOthi4[(size_t)DM*DM/8], g_WOtlo4[(size_t)DM*DM/8];         // [d][n]
__device__ uint4 g_Qhi4 [(size_t)TOK*DM/8], g_Qlo4 [(size_t)TOK*DM/8];  // [b,h,s,d]
__device__ uint4 g_Khi4 [(size_t)TOK*DM/8], g_Klo4 [(size_t)TOK*DM/8];  // [b,h,s,d]
__device__ uint4 g_Vthi4[(size_t)TOK*DM/8], g_Vtlo4[(size_t)TOK*DM/8];  // [b,h,d,s]
__device__ uint4 g_MHhi4[(size_t)TOK*DM/8], g_MHlo4[(size_t)TOK*DM/8];  // [t, h*64+v]

#define BF(p) ((__nv_bfloat16*)(p))

// ---------------------------------------------------------------------------
// Helpers
// ---------------------------------------------------------------------------
__device__ __forceinline__ uint32_t smem_u32(const void* p){
    uint32_t a;
    asm("{ .reg .u64 t; cvta.to.shared.u64 t, %1; cvt.u32.u64 %0, t; }" : "=r"(a) : "l"(p));
    return a;
}
__device__ __forceinline__ void mma_bf16(float* d, const uint32_t* a,
                                         uint32_t b0, uint32_t b1){
    asm volatile("mma.sync.aligned.m16n8k16.row.col.f32.bf16.bf16.f32 "
        "{%0,%1,%2,%3}, {%4,%5,%6,%7}, {%8,%9}, {%0,%1,%2,%3};"
        : "+f"(d[0]), "+f"(d[1]), "+f"(d[2]), "+f"(d[3])
        : "r"(a[0]), "r"(a[1]), "r"(a[2]), "r"(a[3]), "r"(b0), "r"(b1));
}
__device__ __forceinline__ void ldsm4(uint32_t addr, uint32_t* r){
    asm volatile("ldmatrix.sync.aligned.m8n8.x4.shared.b16 {%0,%1,%2,%3}, [%4];"
        : "=r"(r[0]), "=r"(r[1]), "=r"(r[2]), "=r"(r[3]) : "r"(addr));
}
__device__ __forceinline__ void cpa16(uint32_t saddr, const void* g){
    asm volatile("cp.async.cg.shared.global [%0], [%1], 16;" :: "r"(saddr), "l"(g));
}
#define CP_COMMIT() asm volatile("cp.async.commit_group;" ::: "memory")
#define CP_WAIT0()  asm volatile("cp.async.wait_group 0;" ::: "memory")

__device__ __forceinline__ void pack_hilo(float v0, float v1, uint32_t& hi, uint32_t& lo){
    __nv_bfloat162 hp = __floats2bfloat162_rn(v0, v1);
    float l0 = v0 - __bfloat162float(hp.x);
    float l1 = v1 - __bfloat162float(hp.y);
    __nv_bfloat162 lp = __floats2bfloat162_rn(l0, l1);
    hi = *(uint32_t*)&hp; lo = *(uint32_t*)&lp;
}
__device__ __forceinline__ float exp2_fast(float t){
    t = fmaxf(t, -126.f);
    float fi = floorf(t);
    float f = t - fi;
    float p = 1.5403530e-4f;
    p = fmaf(p, f, 1.3333558e-3f);
    p = fmaf(p, f, 9.6181291e-3f);
    p = fmaf(p, f, 5.5504109e-2f);
    p = fmaf(p, f, 2.4022651e-1f);
    p = fmaf(p, f, 6.9314718e-1f);
    p = fmaf(p, f, 1.0f);
    return p * __int_as_float(((int)fi + 127) << 23);
}

// ---------------------------------------------------------------------------
// Prep: fp32 -> bf16 hi/lo (+ weight transposes)
// ---------------------------------------------------------------------------
__global__ __launch_bounds__(256) void prep_x(const float* __restrict__ X){
    int i0 = (blockIdx.x * 256 + threadIdx.x) * 8;
    #pragma unroll
    for (int k = 0; k < 8; k++){
        int i = i0 + k;
        float v = X[i];
        __nv_bfloat16 h = __float2bfloat16(v);
        BF(g_Xhi4)[i] = h;
        BF(g_Xlo4)[i] = __float2bfloat16(v - __bfloat162float(h));
    }
}

__global__ __launch_bounds__(256) void prep_wqkv(const float* __restrict__ WQ,
                                                 const float* __restrict__ WK,
                                                 const float* __restrict__ WV){
    __shared__ float tile[64][65];
    int x = blockIdx.x;               // mat*12 + h
    int mt = blockIdx.y;              // m tile (12)
    int mat = x / NH, h = x % NH;
    const float* src = (mat == 0 ? WQ : mat == 1 ? WK : WV) + (size_t)h * DM * 64;
    int tid = threadIdx.x;
    #pragma unroll
    for (int i = 0; i < 16; i++){
        int idx = tid + i * 256;
        int r = idx >> 6, c = idx & 63;
        tile[r][c] = src[(size_t)(mt * 64 + r) * 64 + c];
    }
    __syncthreads();
    #pragma unroll
    for (int i = 0; i < 16; i++){
        int idx = tid + i * 256;
        int n = idx >> 6, mc = idx & 63;
        float v = tile[mc][n];
        __nv_bfloat16 hh = __float2bfloat16(v);
        size_t o = ((size_t)x * 64 + n) * DM + mt * 64 + mc;
        BF(g_Wthi4)[o] = hh;
        BF(g_Wtlo4)[o] = __float2bfloat16(v - __bfloat162float(hh));
    }
}

__global__ __launch_bounds__(256) void prep_wo(const float* __restrict__ WO){
    __shared__ float tile[64][65];
    int nt = blockIdx.x, dt = blockIdx.y;
    int tid = threadIdx.x;
    #pragma unroll
    for (int i = 0; i < 16; i++){
        int idx = tid + i * 256;
        int r = idx >> 6, c = idx & 63;
        tile[r][c] = WO[(size_t)(nt * 64 + r) * DM + dt * 64 + c];
    }
    __syncthreads();
    #pragma unroll
    for (int i = 0; i < 16; i++){
        int idx = tid + i * 256;
        int dr = idx >> 6, nc = idx & 63;
        float v = tile[nc][dr];
        __nv_bfloat16 hh = __float2bfloat16(v);
        size_t o = (size_t)(dt * 64 + dr) * DM + nt * 64 + nc;
        BF(g_WOthi4)[o] = hh;
        BF(g_WOtlo4)[o] = __float2bfloat16(v - __bfloat162float(hh));
    }
}

// ---------------------------------------------------------------------------
// GEMM: 128x128 tile, K chunks of 32, 8 warps (4m x 2n), cp.async 2-stage,
// ldmatrix fragments. smem per stage: Ah/Al/Bh/Bl, each 128 x 40hw = 10240B.
// ---------------------------------------------------------------------------
#define GSA 40
#define GTILE 10240
#define GSTAGE (4*GTILE)        // 40960
#define GEMM_SMEM (2*GSTAGE)    // 81920

__device__ __forceinline__ void gemm_cpa_chunk(
    const __nv_bfloat16* GA_h, const __nv_bfloat16* GA_l,
    const __nv_bfloat16* GB_h, const __nv_bfloat16* GB_l,
    int arow0, int brow0, int ch, uint32_t sdst, int lrow, int lh)
{
    size_t ga = (size_t)(arow0 + lrow) * DM + ch * 32 + lh * 16;
    size_t gb = (size_t)(brow0 + lrow) * DM + ch * 32 + lh * 16;
    uint32_t so = (uint32_t)((lrow * GSA + lh * 16) * 2);
    cpa16(sdst           + so, GA_h + ga); cpa16(sdst           + so + 16, GA_h + ga + 8);
    cpa16(sdst +   GTILE + so, GA_l + ga); cpa16(sdst +   GTILE + so + 16, GA_l + ga + 8);
    cpa16(sdst + 2*GTILE + so, GB_h + gb); cpa16(sdst + 2*GTILE + so + 16, GB_h + gb + 8);
    cpa16(sdst + 3*GTILE + so, GB_l + gb); cpa16(sdst + 3*GTILE + so + 16, GB_l + gb + 8);
}

__device__ __forceinline__ void gemm_core(
    const __nv_bfloat16* GA_h, const __nv_bfloat16* GA_l,
    const __nv_bfloat16* GB_h, const __nv_bfloat16* GB_l,
    int arow0, int brow0, uint32_t sb,
    int tid, int wm, int wn, int lane,
    float acc[2][8][4])
{
    const int lrow = tid >> 1, lh = tid & 1;
    const int a_r = lane & 15, a_c = (lane & 16) >> 1;
    const int b_r = (lane & 7) + ((lane & 16) >> 1), b_c = lane & 8;

    gemm_cpa_chunk(GA_h, GA_l, GB_h, GB_l, arow0, brow0, 0, sb, lrow, lh);
    CP_COMMIT();

    for (int ch = 0; ch < 24; ch++){
        CP_WAIT0();
        __syncthreads();
        if (ch + 1 < 24){
            gemm_cpa_chunk(GA_h, GA_l, GB_h, GB_l, arow0, brow0, ch + 1,
                           sb + ((ch + 1) & 1) * GSTAGE, lrow, lh);
            CP_COMMIT();
        }
        const uint32_t st = sb + (ch & 1) * GSTAGE;
        #pragma unroll
        for (int k0 = 0; k0 < 32; k0 += 16){
            uint32_t ah[2][4], al[2][4];
            #pragma unroll
            for (int mt = 0; mt < 2; mt++){
                uint32_t ad = st + ((wm * 32 + mt * 16 + a_r) * GSA + k0 + a_c) * 2;
                ldsm4(ad, ah[mt]);
                ldsm4(ad + GTILE, al[mt]);
            }
            #pragma unroll
            for (int p = 0; p < 4; p++){
                uint32_t bd = st + 2 * GTILE +
                              ((wn * 64 + p * 16 + b_r) * GSA + k0 + b_c) * 2;
                uint32_t bh4[4], bl4[4];
                ldsm4(bd, bh4);
                ldsm4(bd + GTILE, bl4);
                #pragma unroll
                for (int mt = 0; mt < 2; mt++){
                    mma_bf16(acc[mt][2*p],   ah[mt], bh4[0], bh4[1]);
                    mma_bf16(acc[mt][2*p],   ah[mt], bl4[0], bl4[1]);
                    mma_bf16(acc[mt][2*p],   al[mt], bh4[0], bh4[1]);
                    mma_bf16(acc[mt][2*p+1], ah[mt], bh4[2], bh4[3]);
                    mma_bf16(acc[mt][2*p+1], ah[mt], bl4[2], bl4[3]);
                    mma_bf16(acc[mt][2*p+1], al[mt], bh4[2], bh4[3]);
                }
            }
        }
    }
}

// QKV projection: A = X[t, m], B = Wt rows
__global__ __launch_bounds__(256) void gemm_qkv(){
    extern __shared__ __align__(16) char smem[];
    const uint32_t sb = smem_u32(smem);
    const int tid = threadIdx.x, w = tid >> 5, lane = tid & 31;
    const int wm = w & 3, wn = w >> 2;
    const int r = lane >> 2, c2 = (lane & 3) * 2;
    const int t0 = blockIdx.x * 128;
    const int j = blockIdx.y;
    const int mat = j / 6, h0 = (j % 6) * 2;
    const int brow0 = (mat * NH + h0) * 64;

    float acc[2][8][4] = {};
    gemm_core(BF(g_Xhi4), BF(g_Xlo4), BF(g_Wthi4), BF(g_Wtlo4),
              t0, brow0, sb, tid, wm, wn, lane, acc);

    const int hh_g = h0 + wn;
    #pragma unroll
    for (int mt = 0; mt < 2; mt++){
        #pragma unroll
        for (int hf = 0; hf < 2; hf++){
            int srow = t0 + wm * 32 + mt * 16 + r + hf * 8;
            int bb = srow >> 11, s = srow & 2047;
            if (mat < 2){
                uint32_t* DH = (uint32_t*)(mat == 0 ? g_Qhi4 : g_Khi4);
                uint32_t* DL = (uint32_t*)(mat == 0 ? g_Qlo4 : g_Klo4);
                size_t base = ((size_t)(bb * NH + hh_g) * SEQ + s) * 32;
                #pragma unroll
                for (int nt = 0; nt < 8; nt++){
                    int d = nt * 8 + c2;
                    uint32_t hi, lo;
                    pack_hilo(acc[mt][nt][hf*2], acc[mt][nt][hf*2+1], hi, lo);
                    DH[base + (d >> 1)] = hi;
                    DL[base + (d >> 1)] = lo;
                }
            } else {
                __nv_bfloat16* VH = BF(g_Vthi4);
                __nv_bfloat16* VL = BF(g_Vtlo4);
                #pragma unroll
                for (int nt = 0; nt < 8; nt++){
                    #pragma unroll
                    for (int j2 = 0; j2 < 2; j2++){
                        int d = nt * 8 + c2 + j2;
                        float v = acc[mt][nt][hf*2+j2];
                        __nv_bfloat16 hb = __float2bfloat16(v);
                        size_t o = ((size_t)(bb * NH + hh_g) * 64 + d) * SEQ + s;
                        VH[o] = hb;
                        VL[o] = __float2bfloat16(v - __bfloat162float(hb));
                    }
                }
            }
        }
    }
}

// Output projection
__global__ __launch_bounds__(256) void gemm_oproj(float* __restrict__ out){
    extern __shared__ __align__(16) char smem[];
    const uint32_t sb = smem_u32(smem);
    const int tid = threadIdx.x, w = tid >> 5, lane = tid & 31;
    const int wm = w & 3, wn = w >> 2;
    const int r = lane >> 2, c2 = (lane & 3) * 2;
    const int t0 = blockIdx.x * 128;
    const int d0 = blockIdx.y * 128;

    float acc[2][8][4] = {};
    gemm_core(BF(g_MHhi4), BF(g_MHlo4), BF(g_WOthi4), BF(g_WOtlo4),
              t0, d0, sb, tid, wm, wn, lane, acc);

    #pragma unroll
    for (int mt = 0; mt < 2; mt++){
        #pragma unroll
        for (int hf = 0; hf < 2; hf++){
            int srow = t0 + wm * 32 + mt * 16 + r + hf * 8;
            #pragma unroll
            for (int nt = 0; nt < 8; nt++){
                int dcol = d0 + wn * 64 + nt * 8 + c2;
                float2 v = make_float2(acc[mt][nt][hf*2], acc[mt][nt][hf*2+1]);
                *(float2*)(out + (size_t)srow * DM + dcol) = v;
            }
        }
    }
}

// ---------------------------------------------------------------------------
// Flash attention: 128-q tile, 64-kv tile, 8 warps (4m x 2n)
// P stays in registers (S-frag == A-frag after bf16 pack); O/l kept as per-wn
// partials, merged once at the end. K/V double-buffered via cp.async.
// smem: Qh 0 (18432), Ql 18432; KV stages at 36864 (+s*36864):
//   Kh 0, Kl 9216, Vh 18432, Vl 27648; redmax at 110592 (2*128 f32)
// ---------------------------------------------------------------------------
#define ASA    72
#define AQTILE 18432
#define AKTILE 9216
#define AT_KV  36864
#define AKVSTG (4*AKTILE)       // 36864
#define AT_RED 110592
#define ATTN_SMEM (AT_RED + 2*128*4)   // 111616

__device__ __forceinline__ void attn_cpa_kv(
    const __nv_bfloat16* KH, const __nv_bfloat16* KL,
    const __nv_bfloat16* VH, const __nv_bfloat16* VL,
    int bh_idx, int jj, uint32_t sdst, int lrow, int lq)
{
    size_t gk = ((size_t)bh_idx * SEQ + jj * 64 + lrow) * 64 + lq * 16;
    size_t gv = ((size_t)(bh_idx * 64 + lrow)) * SEQ + jj * 64 + lq * 16;
    uint32_t so = (uint32_t)((lrow * ASA + lq * 16) * 2);
    cpa16(sdst            + so, KH + gk); cpa16(sdst            + so + 16, KH + gk + 8);
    cpa16(sdst +   AKTILE + so, KL + gk); cpa16(sdst +   AKTILE + so + 16, KL + gk + 8);
    cpa16(sdst + 2*AKTILE + so, VH + gv); cpa16(sdst + 2*AKTILE + so + 16, VH + gv + 8);
    cpa16(sdst + 3*AKTILE + so, VL + gv); cpa16(sdst + 3*AKTILE + so + 16, VL + gv + 8);
}

__global__ __launch_bounds__(256) void attn_kernel(){
    extern __shared__ __align__(16) char smem[];
    const uint32_t sb = smem_u32(smem);
    float* redmax = (float*)(smem + AT_RED);

    const int tid = threadIdx.x, w = tid >> 5, lane = tid & 31;
    const int wm = w & 3, wn = w >> 2;
    const int r = lane >> 2, c2 = (lane & 3) * 2;
    const int a_r = lane & 15, a_c = (lane & 16) >> 1;
    const int b_r = (lane & 7) + ((lane & 16) >> 1), b_c = lane & 8;

    const int qt = 15 - blockIdx.x;   // heavy tiles first
    const int pr = blockIdx.y;
    const int b = pr / NH, h = pr % NH;
    const int bh_idx = b * NH + h;
    const int jmax = 2 * qt + 1;

    const __nv_bfloat16* QH = BF(g_Qhi4);
    const __nv_bfloat16* QL = BF(g_Qlo4);
    const __nv_bfloat16* KH = BF(g_Khi4);
    const __nv_bfloat16* KL = BF(g_Klo4);
    const __nv_bfloat16* VH = BF(g_Vthi4);
    const __nv_bfloat16* VL = BF(g_Vtlo4);

    const int lrowQ = tid >> 1, lhQ = tid & 1;
    const int lrowK = tid >> 2, lqK = tid & 3;

    // prologue: Q + KV stage 0
    {
        size_t gq = ((size_t)bh_idx * SEQ + qt * 128 + lrowQ) * 64 + lhQ * 32;
        uint32_t so = (uint32_t)((lrowQ * ASA + lhQ * 32) * 2);
        #pragma unroll
        for (int i = 0; i < 4; i++){
            cpa16(sb          + so + i * 16, QH + gq + i * 8);
            cpa16(sb + AQTILE + so + i * 16, QL + gq + i * 8);
        }
        attn_cpa_kv(KH, KL, VH, VL, bh_idx, 0, sb + AT_KV, lrowK, lqK);
        CP_COMMIT();
    }

    float O[2][8][4] = {};
    float m_i[2][2] = {{-1e30f, -1e30f}, {-1e30f, -1e30f}};
    float l_i[2][2] = {};
    const float CSC = 0.125f * 1.4426950408889634f;

    for (int jj = 0; jj <= jmax; jj++){
        CP_WAIT0();
        __syncthreads();
        if (jj + 1 <= jmax){
            attn_cpa_kv(KH, KL, VH, VL, bh_idx, jj + 1,
                        sb + AT_KV + ((jj + 1) & 1) * AKVSTG, lrowK, lqK);
            CP_COMMIT();
        }
        const uint32_t stk = sb + AT_KV + (jj & 1) * AKVSTG;

        // ---- S = Q K^T (3-term) ----
        float sacc[2][4][4] = {};
        #pragma unroll
        for (int kc = 0; kc < 4; kc++){
            const int k0 = kc * 16;
            uint32_t qh4[2][4], ql4[2][4];
            #pragma unroll
            for (int mt = 0; mt < 2; mt++){
                uint32_t qa = sb + ((wm * 32 + mt * 16 + a_r) * ASA + k0 + a_c) * 2;
                ldsm4(qa, qh4[mt]);
                ldsm4(qa + AQTILE, ql4[mt]);
            }
            #pragma unroll
            for (int p = 0; p < 2; p++){
                uint32_t ka = stk + ((wn * 32 + p * 16 + b_r) * ASA + k0 + b_c) * 2;
                uint32_t kh4[4], kl4[4];
                ldsm4(ka, kh4);
                ldsm4(ka + AKTILE, kl4);
                #pragma unroll
                for (int mt = 0; mt < 2; mt++){
                    mma_bf16(sacc[mt][2*p],   qh4[mt], kh4[0], kh4[1]);
                    mma_bf16(sacc[mt][2*p],   qh4[mt], kl4[0], kl4[1]);
                    mma_bf16(sacc[mt][2*p],   ql4[mt], kh4[0], kh4[1]);
                    mma_bf16(sacc[mt][2*p+1], qh4[mt], kh4[2], kh4[3]);
                    mma_bf16(sacc[mt][2*p+1], qh4[mt], kl4[2], kl4[3]);
                    mma_bf16(sacc[mt][2*p+1], ql4[mt], kh4[2], kh4[3]);
                }
            }
        }

        // ---- scale + mask + row max -> redmax ----
        #pragma unroll
        for (int mt = 0; mt < 2; mt++){
            #pragma unroll
            for (int hf = 0; hf < 2; hf++){
                int row = wm * 32 + mt * 16 + hf * 8 + r;
                int qrow = qt * 128 + row;
                float mx = -1e30f;
                #pragma unroll
                for (int nt = 0; nt < 4; nt++){
                    #pragma unroll
                    for (int j2 = 0; j2 < 2; j2++){
                        int col = jj * 64 + wn * 32 + nt * 8 + c2 + j2;
                        float v = sacc[mt][nt][hf*2+j2] * CSC;
                        if (col > qrow) v = -1e30f;
                        sacc[mt][nt][hf*2+j2] = v;
                        mx = fmaxf(mx, v);
                    }
                }
                mx = fmaxf(mx, __shfl_xor_sync(0xffffffffu, mx, 1));
                mx = fmaxf(mx, __shfl_xor_sync(0xffffffffu, mx, 2));
                if ((lane & 3) == 0) redmax[wn * 128 + row] = mx;
            }
        }
        __syncthreads();

        // ---- softmax: exp, per-warp l partial, O rescale, P pack ----
        #pragma unroll
        for (int mt = 0; mt < 2; mt++){
            #pragma unroll
            for (int hf = 0; hf < 2; hf++){
                int row = wm * 32 + mt * 16 + hf * 8 + r;
                float mn = fmaxf(m_i[mt][hf], fmaxf(redmax[row], redmax[128 + row]));
                float alpha = exp2_fast(m_i[mt][hf] - mn);
                m_i[mt][hf] = mn;
                float rs = 0.f;
                #pragma unroll
                for (int nt = 0; nt < 4; nt++){
                    #pragma unroll
                    for (int j2 = 0; j2 < 2; j2++){
                        float p = exp2_fast(sacc[mt][nt][hf*2+j2] - mn);
                        sacc[mt][nt][hf*2+j2] = p;
                        rs += p;
                    }
                }
                rs += __shfl_xor_sync(0xffffffffu, rs, 1);
                rs += __shfl_xor_sync(0xffffffffu, rs, 2);
                l_i[mt][hf] = l_i[mt][hf] * alpha + rs;
                #pragma unroll
                for (int nt = 0; nt < 8; nt++){
                    O[mt][nt][hf*2]   *= alpha;
                    O[mt][nt][hf*2+1] *= alpha;
                }
            }
        }

        // P fragments (register-only): A-frag layout from sacc
        uint32_t pha[2][2][4], pla[2][2][4];
        #pragma unroll
        for (int mt = 0; mt < 2; mt++){
            #pragma unroll
            for (int kc2 = 0; kc2 < 2; kc2++){
                pack_hilo(sacc[mt][2*kc2][0],   sacc[mt][2*kc2][1],   pha[mt][kc2][0], pla[mt][kc2][0]);
                pack_hilo(sacc[mt][2*kc2][2],   sacc[mt][2*kc2][3],   pha[mt][kc2][1], pla[mt][kc2][1]);
                pack_hilo(sacc[mt][2*kc2+1][0], sacc[mt][2*kc2+1][1], pha[mt][kc2][2], pla[mt][kc2][2]);
                pack_hilo(sacc[mt][2*kc2+1][2], sacc[mt][2*kc2+1][3], pha[mt][kc2][3], pla[mt][kc2][3]);
            }
        }

        // ---- PV: O partial over this warp's 32-kv slice, all 64 v cols ----
        #pragma unroll
        for (int kc2 = 0; kc2 < 2; kc2++){
            const int k0v = wn * 32 + kc2 * 16;
            #pragma unroll
            for (int p = 0; p < 4; p++){
                uint32_t va = stk + 2 * AKTILE + ((p * 16 + b_r) * ASA + k0v + b_c) * 2;
                uint32_t vh4[4], vl4[4];
                ldsm4(va, vh4);
                ldsm4(va + AKTILE, vl4);
                #pragma unroll
                for (int mt = 0; mt < 2; mt++){
                    mma_bf16(O[mt][2*p],   pha[mt][kc2], vh4[0], vh4[1]);
                    mma_bf16(O[mt][2*p],   pha[mt][kc2], vl4[0], vl4[1]);
                    mma_bf16(O[mt][2*p],   pla[mt][kc2], vh4[0], vh4[1]);
                    mma_bf16(O[mt][2*p+1], pha[mt][kc2], vh4[2], vh4[3]);
                    mma_bf16(O[mt][2*p+1], pha[mt][kc2], vl4[2], vl4[3]);
                    mma_bf16(O[mt][2*p+1], pla[mt][kc2], vh4[2], vh4[3]);
                }
            }
        }
    }

    // ---- merge wn partials, normalize, write MH hi/lo ----
    __syncthreads();
    float* exO = (float*)smem;                     // [128][66]
    float* exL = (float*)(smem + 128 * 66 * 4);    // [128]
    if (wn == 1){
        #pragma unroll
        for (int mt = 0; mt < 2; mt++){
            #pragma unroll
            for (int hf = 0; hf < 2; hf++){
                int row = wm * 32 + mt * 16 + hf * 8 + r;
                #pragma unroll
                for (int nt = 0; nt < 8; nt++){
                    exO[row * 66 + nt * 8 + c2]     = O[mt][nt][hf*2];
                    exO[row * 66 + nt * 8 + c2 + 1] = O[mt][nt][hf*2+1];
                }
                if ((lane & 3) == 0) exL[row] = l_i[mt][hf];
            }
        }
    }
    __syncthreads();
    if (wn == 0){
        uint32_t* MHH = (uint32_t*)g_MHhi4;
        uint32_t* MHL = (uint32_t*)g_MHlo4;
        #pragma unroll
        for (int mt = 0; mt < 2; mt++){
            #pragma unroll
            for (int hf = 0; hf < 2; hf++){
                int row = wm * 32 + mt * 16 + hf * 8 + r;
                float linv = 1.f / (l_i[mt][hf] + exL[row]);
                size_t t = (size_t)b * SEQ + qt * 128 + row;
                #pragma unroll
                for (int nt = 0; nt < 8; nt++){
                    float v0 = (O[mt][nt][hf*2]   + exO[row * 66 + nt * 8 + c2])     * linv;
                    float v1 = (O[mt][nt][hf*2+1] + exO[row * 66 + nt * 8 + c2 + 1]) * linv;
                    uint32_t hi, lo;
                    pack_hilo(v0, v1, hi, lo);
                    size_t col = h * 64 + nt * 8 + c2;
                    MHH[(t * DM + col) >> 1] = hi;
                    MHL[(t * DM + col) >> 1] = lo;
                }
            }
        }
    }
}

// ---------------------------------------------------------------------------
extern "C" void kernel_launch(void* const* d_in, const int* in_sizes, int n_in,
                              void* d_out, int out_size)
{
    const float* residual = (const float*)d_in[0];
    const float* W_Q = (const float*)d_in[1];
    const float* W_K = (const float*)d_in[2];
    const float* W_V = (const float*)d_in[3];
    const float* W_O = (const float*)d_in[4];
    float* out = (float*)d_out;

    cudaFuncSetAttribute(gemm_qkv,   cudaFuncAttributeMaxDynamicSharedMemorySize, GEMM_SMEM);
    cudaFuncSetAttribute(gemm_oproj, cudaFuncAttributeMaxDynamicSharedMemorySize, GEMM_SMEM);
    cudaFuncSetAttribute(attn_kernel, cudaFuncAttributeMaxDynamicSharedMemorySize, ATTN_SMEM);

    prep_x<<<TOK * DM / (256 * 8), 256>>>(residual);
    prep_wqkv<<<dim3(3 * NH, 12), 256>>>(W_Q, W_K, W_V);
    prep_wo<<<dim3(12, 12), 256>>>(W_O);

    gemm_qkv<<<dim3(64, 18), 256, GEMM_SMEM>>>();
    attn_kernel<<<dim3(16, BATCH * NH), 256, ATTN_SMEM>>>();
    gemm_oproj<<<dim3(64, 6), 256, GEMM_SMEM>>>(out);
}

// round 7
// speedup vs baseline: 4.6050x; 1.0682x over previous
#include <cuda_runtime.h>
#include <cuda_bf16.h>
#include <cstdint>

#define BATCH 4
#define SEQ   2048
#define DM    768
#define NH    12
#define TOK   (BATCH*SEQ)   // 8192

// ---------------------------------------------------------------------------
// Scratch (uint4 for guaranteed 16B alignment; cast as needed)
// ---------------------------------------------------------------------------
__device__ uint4 g_Xhi4 [(size_t)TOK*DM/8],  g_Xlo4 [(size_t)TOK*DM/8];
__device__ uint4 g_Wthi4[(size_t)3*NH*64*DM/8], g_Wtlo4[(size_t)3*NH*64*DM/8]; // [mat*NH+h][n][m]
__device__ uint4 g_WOthi4[(size_t)DM*DM/8], g_WOtlo4[(size_t)DM*DM/8];         // [d][n]
__device__ uint4 g_Qhi4 [(size_t)TOK*DM/8], g_Qlo4 [(size_t)TOK*DM/8];  // [b,h,s,d]
__device__ uint4 g_Khi4 [(size_t)TOK*DM/8], g_Klo4 [(size_t)TOK*DM/8];  // [b,h,s,d]
__device__ uint4 g_Vthi4[(size_t)TOK*DM/8], g_Vtlo4[(size_t)TOK*DM/8];  // [b,h,d,s]
__device__ uint4 g_MHhi4[(size_t)TOK*DM/8], g_MHlo4[(size_t)TOK*DM/8];  // [t, h*64+v]

#define BF(p) ((__nv_bfloat16*)(p))

// ---------------------------------------------------------------------------
// Helpers
// ---------------------------------------------------------------------------
__device__ __forceinline__ uint32_t smem_u32(const void* p){
    uint32_t a;
    asm("{ .reg .u64 t; cvta.to.shared.u64 t, %1; cvt.u32.u64 %0, t; }" : "=r"(a) : "l"(p));
    return a;
}
__device__ __forceinline__ void mma_bf16(float* d, const uint32_t* a,
                                         uint32_t b0, uint32_t b1){
    asm volatile("mma.sync.aligned.m16n8k16.row.col.f32.bf16.bf16.f32 "
        "{%0,%1,%2,%3}, {%4,%5,%6,%7}, {%8,%9}, {%0,%1,%2,%3};"
        : "+f"(d[0]), "+f"(d[1]), "+f"(d[2]), "+f"(d[3])
        : "r"(a[0]), "r"(a[1]), "r"(a[2]), "r"(a[3]), "r"(b0), "r"(b1));
}
__device__ __forceinline__ void ldsm4(uint32_t addr, uint32_t* r){
    asm volatile("ldmatrix.sync.aligned.m8n8.x4.shared.b16 {%0,%1,%2,%3}, [%4];"
        : "=r"(r[0]), "=r"(r[1]), "=r"(r[2]), "=r"(r[3]) : "r"(addr));
}
__device__ __forceinline__ void cpa16(uint32_t saddr, const void* g){
    asm volatile("cp.async.cg.shared.global [%0], [%1], 16;" :: "r"(saddr), "l"(g));
}
#define CP_COMMIT() asm volatile("cp.async.commit_group;" ::: "memory")
#define CP_WAIT0()  asm volatile("cp.async.wait_group 0;" ::: "memory")

__device__ __forceinline__ void pack_hilo(float v0, float v1, uint32_t& hi, uint32_t& lo){
    __nv_bfloat162 hp = __floats2bfloat162_rn(v0, v1);
    float l0 = v0 - __bfloat162float(hp.x);
    float l1 = v1 - __bfloat162float(hp.y);
    __nv_bfloat162 lp = __floats2bfloat162_rn(l0, l1);
    hi = *(uint32_t*)&hp; lo = *(uint32_t*)&lp;
}
__device__ __forceinline__ float exp2_fast(float t){
    t = fmaxf(t, -126.f);
    float fi = floorf(t);
    float f = t - fi;
    float p = 1.5403530e-4f;
    p = fmaf(p, f, 1.3333558e-3f);
    p = fmaf(p, f, 9.6181291e-3f);
    p = fmaf(p, f, 5.5504109e-2f);
    p = fmaf(p, f, 2.4022651e-1f);
    p = fmaf(p, f, 6.9314718e-1f);
    p = fmaf(p, f, 1.0f);
    return p * __int_as_float(((int)fi + 127) << 23);
}

// ---------------------------------------------------------------------------
// Prep: fp32 -> bf16 hi/lo (+ weight transposes)
// ---------------------------------------------------------------------------
__global__ __launch_bounds__(256) void prep_x(const float* __restrict__ X){
    int i0 = (blockIdx.x * 256 + threadIdx.x) * 8;
    #pragma unroll
    for (int k = 0; k < 8; k++){
        int i = i0 + k;
        float v = X[i];
        __nv_bfloat16 h = __float2bfloat16(v);
        BF(g_Xhi4)[i] = h;
        BF(g_Xlo4)[i] = __float2bfloat16(v - __bfloat162float(h));
    }
}

__global__ __launch_bounds__(256) void prep_wqkv(const float* __restrict__ WQ,
                                                 const float* __restrict__ WK,
                                                 const float* __restrict__ WV){
    __shared__ float tile[64][65];
    int x = blockIdx.x;               // mat*12 + h
    int mt = blockIdx.y;              // m tile (12)
    int mat = x / NH, h = x % NH;
    const float* src = (mat == 0 ? WQ : mat == 1 ? WK : WV) + (size_t)h * DM * 64;
    int tid = threadIdx.x;
    #pragma unroll
    for (int i = 0; i < 16; i++){
        int idx = tid + i * 256;
        int r = idx >> 6, c = idx & 63;
        tile[r][c] = src[(size_t)(mt * 64 + r) * 64 + c];
    }
    __syncthreads();
    #pragma unroll
    for (int i = 0; i < 16; i++){
        int idx = tid + i * 256;
        int n = idx >> 6, mc = idx & 63;
        float v = tile[mc][n];
        __nv_bfloat16 hh = __float2bfloat16(v);
        size_t o = ((size_t)x * 64 + n) * DM + mt * 64 + mc;
        BF(g_Wthi4)[o] = hh;
        BF(g_Wtlo4)[o] = __float2bfloat16(v - __bfloat162float(hh));
    }
}

__global__ __launch_bounds__(256) void prep_wo(const float* __restrict__ WO){
    __shared__ float tile[64][65];
    int nt = blockIdx.x, dt = blockIdx.y;
    int tid = threadIdx.x;
    #pragma unroll
    for (int i = 0; i < 16; i++){
        int idx = tid + i * 256;
        int r = idx >> 6, c = idx & 63;
        tile[r][c] = WO[(size_t)(nt * 64 + r) * DM + dt * 64 + c];
    }
    __syncthreads();
    #pragma unroll
    for (int i = 0; i < 16; i++){
        int idx = tid + i * 256;
        int dr = idx >> 6, nc = idx & 63;
        float v = tile[nc][dr];
        __nv_bfloat16 hh = __float2bfloat16(v);
        size_t o = (size_t)(dt * 64 + dr) * DM + nt * 64 + nc;
        BF(g_WOthi4)[o] = hh;
        BF(g_WOtlo4)[o] = __float2bfloat16(v - __bfloat162float(hh));
    }
}

// ---------------------------------------------------------------------------
// GEMM: 128x128 tile, K chunks of 32, 8 warps (4m x 2n), cp.async 2-stage,
// ldmatrix fragments. smem per stage: Ah/Al/Bh/Bl, each 128 x 40hw = 10240B.
// 2 CTAs/SM (launch_bounds minBlocks=2, regs capped at 128).
// ---------------------------------------------------------------------------
#define GSA 40
#define GTILE 10240
#define GSTAGE (4*GTILE)        // 40960
#define GEMM_SMEM (2*GSTAGE)    // 81920

__device__ __forceinline__ void gemm_cpa_chunk(
    const __nv_bfloat16* GA_h, const __nv_bfloat16* GA_l,
    const __nv_bfloat16* GB_h, const __nv_bfloat16* GB_l,
    int arow0, int brow0, int ch, uint32_t sdst, int lrow, int lh)
{
    size_t ga = (size_t)(arow0 + lrow) * DM + ch * 32 + lh * 16;
    size_t gb = (size_t)(brow0 + lrow) * DM + ch * 32 + lh * 16;
    uint32_t so = (uint32_t)((lrow * GSA + lh * 16) * 2);
    cpa16(sdst           + so, GA_h + ga); cpa16(sdst           + so + 16, GA_h + ga + 8);
    cpa16(sdst +   GTILE + so, GA_l + ga); cpa16(sdst +   GTILE + so + 16, GA_l + ga + 8);
    cpa16(sdst + 2*GTILE + so, GB_h + gb); cpa16(sdst + 2*GTILE + so + 16, GB_h + gb + 8);
    cpa16(sdst + 3*GTILE + so, GB_l + gb); cpa16(sdst + 3*GTILE + so + 16, GB_l + gb + 8);
}

__device__ __forceinline__ void gemm_core(
    const __nv_bfloat16* GA_h, const __nv_bfloat16* GA_l,
    const __nv_bfloat16* GB_h, const __nv_bfloat16* GB_l,
    int arow0, int brow0, uint32_t sb,
    int tid, int wm, int wn, int lane,
    float acc[2][8][4])
{
    const int lrow = tid >> 1, lh = tid & 1;
    const int a_r = lane & 15, a_c = (lane & 16) >> 1;
    const int b_r = (lane & 7) + ((lane & 16) >> 1), b_c = lane & 8;

    gemm_cpa_chunk(GA_h, GA_l, GB_h, GB_l, arow0, brow0, 0, sb, lrow, lh);
    CP_COMMIT();

    for (int ch = 0; ch < 24; ch++){
        CP_WAIT0();
        __syncthreads();
        if (ch + 1 < 24){
            gemm_cpa_chunk(GA_h, GA_l, GB_h, GB_l, arow0, brow0, ch + 1,
                           sb + ((ch + 1) & 1) * GSTAGE, lrow, lh);
            CP_COMMIT();
        }
        const uint32_t st = sb + (ch & 1) * GSTAGE;
        #pragma unroll
        for (int k0 = 0; k0 < 32; k0 += 16){
            uint32_t ah[2][4], al[2][4];
            #pragma unroll
            for (int mt = 0; mt < 2; mt++){
                uint32_t ad = st + ((wm * 32 + mt * 16 + a_r) * GSA + k0 + a_c) * 2;
                ldsm4(ad, ah[mt]);
                ldsm4(ad + GTILE, al[mt]);
            }
            #pragma unroll
            for (int p = 0; p < 4; p++){
                uint32_t bd = st + 2 * GTILE +
                              ((wn * 64 + p * 16 + b_r) * GSA + k0 + b_c) * 2;
                uint32_t bh4[4], bl4[4];
                ldsm4(bd, bh4);
                ldsm4(bd + GTILE, bl4);
                #pragma unroll
                for (int mt = 0; mt < 2; mt++){
                    mma_bf16(acc[mt][2*p],   ah[mt], bh4[0], bh4[1]);
                    mma_bf16(acc[mt][2*p],   ah[mt], bl4[0], bl4[1]);
                    mma_bf16(acc[mt][2*p],   al[mt], bh4[0], bh4[1]);
                    mma_bf16(acc[mt][2*p+1], ah[mt], bh4[2], bh4[3]);
                    mma_bf16(acc[mt][2*p+1], ah[mt], bl4[2], bl4[3]);
                    mma_bf16(acc[mt][2*p+1], al[mt], bh4[2], bh4[3]);
                }
            }
        }
    }
}

// QKV projection: A = X[t, m], B = Wt rows
__global__ __launch_bounds__(256, 2) void gemm_qkv(){
    extern __shared__ __align__(16) char smem[];
    const uint32_t sb = smem_u32(smem);
    const int tid = threadIdx.x, w = tid >> 5, lane = tid & 31;
    const int wm = w & 3, wn = w >> 2;
    const int r = lane >> 2, c2 = (lane & 3) * 2;
    const int t0 = blockIdx.x * 128;
    const int j = blockIdx.y;
    const int mat = j / 6, h0 = (j % 6) * 2;
    const int brow0 = (mat * NH + h0) * 64;

    float acc[2][8][4] = {};
    gemm_core(BF(g_Xhi4), BF(g_Xlo4), BF(g_Wthi4), BF(g_Wtlo4),
              t0, brow0, sb, tid, wm, wn, lane, acc);

    const int hh_g = h0 + wn;
    #pragma unroll
    for (int mt = 0; mt < 2; mt++){
        #pragma unroll
        for (int hf = 0; hf < 2; hf++){
            int srow = t0 + wm * 32 + mt * 16 + r + hf * 8;
            int bb = srow >> 11, s = srow & 2047;
            if (mat < 2){
                uint32_t* DH = (uint32_t*)(mat == 0 ? g_Qhi4 : g_Khi4);
                uint32_t* DL = (uint32_t*)(mat == 0 ? g_Qlo4 : g_Klo4);
                size_t base = ((size_t)(bb * NH + hh_g) * SEQ + s) * 32;
                #pragma unroll
                for (int nt = 0; nt < 8; nt++){
                    int d = nt * 8 + c2;
                    uint32_t hi, lo;
                    pack_hilo(acc[mt][nt][hf*2], acc[mt][nt][hf*2+1], hi, lo);
                    DH[base + (d >> 1)] = hi;
                    DL[base + (d >> 1)] = lo;
                }
            } else {
                __nv_bfloat16* VH = BF(g_Vthi4);
                __nv_bfloat16* VL = BF(g_Vtlo4);
                #pragma unroll
                for (int nt = 0; nt < 8; nt++){
                    #pragma unroll
                    for (int j2 = 0; j2 < 2; j2++){
                        int d = nt * 8 + c2 + j2;
                        float v = acc[mt][nt][hf*2+j2];
                        __nv_bfloat16 hb = __float2bfloat16(v);
                        size_t o = ((size_t)(bb * NH + hh_g) * 64 + d) * SEQ + s;
                        VH[o] = hb;
                        VL[o] = __float2bfloat16(v - __bfloat162float(hb));
                    }
                }
            }
        }
    }
}

// Output projection
__global__ __launch_bounds__(256, 2) void gemm_oproj(float* __restrict__ out){
    extern __shared__ __align__(16) char smem[];
    const uint32_t sb = smem_u32(smem);
    const int tid = threadIdx.x, w = tid >> 5, lane = tid & 31;
    const int wm = w & 3, wn = w >> 2;
    const int r = lane >> 2, c2 = (lane & 3) * 2;
    const int t0 = blockIdx.x * 128;
    const int d0 = blockIdx.y * 128;

    float acc[2][8][4] = {};
    gemm_core(BF(g_MHhi4), BF(g_MHlo4), BF(g_WOthi4), BF(g_WOtlo4),
              t0, d0, sb, tid, wm, wn, lane, acc);

    #pragma unroll
    for (int mt = 0; mt < 2; mt++){
        #pragma unroll
        for (int hf = 0; hf < 2; hf++){
            int srow = t0 + wm * 32 + mt * 16 + r + hf * 8;
            #pragma unroll
            for (int nt = 0; nt < 8; nt++){
                int dcol = d0 + wn * 64 + nt * 8 + c2;
                float2 v = make_float2(acc[mt][nt][hf*2], acc[mt][nt][hf*2+1]);
                *(float2*)(out + (size_t)srow * DM + dcol) = v;
            }
        }
    }
}

// ---------------------------------------------------------------------------
// Flash attention: 128-q tile, 64-kv tile, 8 warps (4m x 2n)
// P stays in registers; O/l per-wn partials merged at end. K/V double-buffered.
// Stride 72 halfwords (64 cols + 8 pad). smem 111616B; 2 CTAs/SM via
// launch_bounds(256,2) (223KB < 228KB carveout; regs capped 128).
//   Q: hi 0, lo 18432 | KV stages at 36864 (+s*36864):
//     Kh 0, Kl 9216, Vh 18432, Vl 27648 | redmax at 110592
// ---------------------------------------------------------------------------
#define ASA    72
#define AQTILE 18432
#define AKTILE 9216
#define AT_KV  36864
#define AKVSTG (4*AKTILE)       // 36864
#define AT_RED 110592
#define ATTN_SMEM (AT_RED + 2*128*4)   // 111616

__device__ __forceinline__ void attn_cpa_kv(
    const __nv_bfloat16* KH, const __nv_bfloat16* KL,
    const __nv_bfloat16* VH, const __nv_bfloat16* VL,
    int bh_idx, int jj, uint32_t sdst, int lrow, int lq)
{
    size_t gk = ((size_t)bh_idx * SEQ + jj * 64 + lrow) * 64 + lq * 16;
    size_t gv = ((size_t)(bh_idx * 64 + lrow)) * SEQ + jj * 64 + lq * 16;
    uint32_t so = (uint32_t)((lrow * ASA + lq * 16) * 2);
    cpa16(sdst            + so, KH + gk); cpa16(sdst            + so + 16, KH + gk + 8);
    cpa16(sdst +   AKTILE + so, KL + gk); cpa16(sdst +   AKTILE + so + 16, KL + gk + 8);
    cpa16(sdst + 2*AKTILE + so, VH + gv); cpa16(sdst + 2*AKTILE + so + 16, VH + gv + 8);
    cpa16(sdst + 3*AKTILE + so, VL + gv); cpa16(sdst + 3*AKTILE + so + 16, VL + gv + 8);
}

__global__ __launch_bounds__(256, 2) void attn_kernel(){
    extern __shared__ __align__(16) char smem[];
    const uint32_t sb = smem_u32(smem);
    float* redmax = (float*)(smem + AT_RED);

    const int tid = threadIdx.x, w = tid >> 5, lane = tid & 31;
    const int wm = w & 3, wn = w >> 2;
    const int r = lane >> 2, c2 = (lane & 3) * 2;
    const int a_r = lane & 15, a_c = (lane & 16) >> 1;
    const int b_r = (lane & 7) + ((lane & 16) >> 1), b_c = lane & 8;

    const int qt = 15 - blockIdx.x;   // heavy tiles first
    const int pr = blockIdx.y;
    const int b = pr / NH, h = pr % NH;
    const int bh_idx = b * NH + h;
    const int jmax = 2 * qt + 1;

    const __nv_bfloat16* QH = BF(g_Qhi4);
    const __nv_bfloat16* QL = BF(g_Qlo4);
    const __nv_bfloat16* KH = BF(g_Khi4);
    const __nv_bfloat16* KL = BF(g_Klo4);
    const __nv_bfloat16* VH = BF(g_Vthi4);
    const __nv_bfloat16* VL = BF(g_Vtlo4);

    const int lrowQ = tid >> 1, lhQ = tid & 1;
    const int lrowK = tid >> 2, lqK = tid & 3;

    // prologue: Q + KV stage 0
    {
        size_t gq = ((size_t)bh_idx * SEQ + qt * 128 + lrowQ) * 64 + lhQ * 32;
        uint32_t so = (uint32_t)((lrowQ * ASA + lhQ * 32) * 2);
        #pragma unroll
        for (int i = 0; i < 4; i++){
            cpa16(sb          + so + i * 16, QH + gq + i * 8);
            cpa16(sb + AQTILE + so + i * 16, QL + gq + i * 8);
        }
        attn_cpa_kv(KH, KL, VH, VL, bh_idx, 0, sb + AT_KV, lrowK, lqK);
        CP_COMMIT();
    }

    float O[2][8][4] = {};
    float m_i[2][2] = {{-1e30f, -1e30f}, {-1e30f, -1e30f}};
    float l_i[2][2] = {};
    const float CSC = 0.125f * 1.4426950408889634f;

    for (int jj = 0; jj <= jmax; jj++){
        CP_WAIT0();
        __syncthreads();
        if (jj + 1 <= jmax){
            attn_cpa_kv(KH, KL, VH, VL, bh_idx, jj + 1,
                        sb + AT_KV + ((jj + 1) & 1) * AKVSTG, lrowK, lqK);
            CP_COMMIT();
        }
        const uint32_t stk = sb + AT_KV + (jj & 1) * AKVSTG;

        // ---- S = Q K^T (3-term) ----
        float sacc[2][4][4] = {};
        #pragma unroll
        for (int kc = 0; kc < 4; kc++){
            const int k0 = kc * 16;
            uint32_t qh4[2][4], ql4[2][4];
            #pragma unroll
            for (int mt = 0; mt < 2; mt++){
                uint32_t qa = sb + ((wm * 32 + mt * 16 + a_r) * ASA + k0 + a_c) * 2;
                ldsm4(qa, qh4[mt]);
                ldsm4(qa + AQTILE, ql4[mt]);
            }
            #pragma unroll
            for (int p = 0; p < 2; p++){
                uint32_t ka = stk + ((wn * 32 + p * 16 + b_r) * ASA + k0 + b_c) * 2;
                uint32_t kh4[4], kl4[4];
                ldsm4(ka, kh4);
                ldsm4(ka + AKTILE, kl4);
                #pragma unroll
                for (int mt = 0; mt < 2; mt++){
                    mma_bf16(sacc[mt][2*p],   qh4[mt], kh4[0], kh4[1]);
                    mma_bf16(sacc[mt][2*p],   qh4[mt], kl4[0], kl4[1]);
                    mma_bf16(sacc[mt][2*p],   ql4[mt], kh4[0], kh4[1]);
                    mma_bf16(sacc[mt][2*p+1], qh4[mt], kh4[2], kh4[3]);
                    mma_bf16(sacc[mt][2*p+1], qh4[mt], kl4[2], kl4[3]);
                    mma_bf16(sacc[mt][2*p+1], ql4[mt], kh4[2], kh4[3]);
                }
            }
        }

        // ---- scale + mask + row max -> redmax ----
        #pragma unroll
        for (int mt = 0; mt < 2; mt++){
            #pragma unroll
            for (int hf = 0; hf < 2; hf++){
                int row = wm * 32 + mt * 16 + hf * 8 + r;
                int qrow = qt * 128 + row;
                float mx = -1e30f;
                #pragma unroll
                for (int nt = 0; nt < 4; nt++){
                    #pragma unroll
                    for (int j2 = 0; j2 < 2; j2++){
                        int col = jj * 64 + wn * 32 + nt * 8 + c2 + j2;
                        float v = sacc[mt][nt][hf*2+j2] * CSC;
                        if (col > qrow) v = -1e30f;
                        sacc[mt][nt][hf*2+j2] = v;
                        mx = fmaxf(mx, v);
                    }
                }
                mx = fmaxf(mx, __shfl_xor_sync(0xffffffffu, mx, 1));
                mx = fmaxf(mx, __shfl_xor_sync(0xffffffffu, mx, 2));
                if ((lane & 3) == 0) redmax[wn * 128 + row] = mx;
            }
        }
        __syncthreads();

        // ---- softmax: exp, per-warp l partial, O rescale, P pack ----
        #pragma unroll
        for (int mt = 0; mt < 2; mt++){
            #pragma unroll
            for (int hf = 0; hf < 2; hf++){
                int row = wm * 32 + mt * 16 + hf * 8 + r;
                float mn = fmaxf(m_i[mt][hf], fmaxf(redmax[row], redmax[128 + row]));
                float alpha = exp2_fast(m_i[mt][hf] - mn);
                m_i[mt][hf] = mn;
                float rs = 0.f;
                #pragma unroll
                for (int nt = 0; nt < 4; nt++){
                    #pragma unroll
                    for (int j2 = 0; j2 < 2; j2++){
                        float p = exp2_fast(sacc[mt][nt][hf*2+j2] - mn);
                        sacc[mt][nt][hf*2+j2] = p;
                        rs += p;
                    }
                }
                rs += __shfl_xor_sync(0xffffffffu, rs, 1);
                rs += __shfl_xor_sync(0xffffffffu, rs, 2);
                l_i[mt][hf] = l_i[mt][hf] * alpha + rs;
                #pragma unroll
                for (int nt = 0; nt < 8; nt++){
                    O[mt][nt][hf*2]   *= alpha;
                    O[mt][nt][hf*2+1] *= alpha;
                }
            }
        }

        // P fragments (register-only): A-frag layout from sacc
        uint32_t pha[2][2][4], pla[2][2][4];
        #pragma unroll
        for (int mt = 0; mt < 2; mt++){
            #pragma unroll
            for (int kc2 = 0; kc2 < 2; kc2++){
                pack_hilo(sacc[mt][2*kc2][0],   sacc[mt][2*kc2][1],   pha[mt][kc2][0], pla[mt][kc2][0]);
                pack_hilo(sacc[mt][2*kc2][2],   sacc[mt][2*kc2][3],   pha[mt][kc2][1], pla[mt][kc2][1]);
                pack_hilo(sacc[mt][2*kc2+1][0], sacc[mt][2*kc2+1][1], pha[mt][kc2][2], pla[mt][kc2][2]);
                pack_hilo(sacc[mt][2*kc2+1][2], sacc[mt][2*kc2+1][3], pha[mt][kc2][3], pla[mt][kc2][3]);
            }
        }

        // ---- PV: O partial over this warp's 32-kv slice, all 64 v cols ----
        #pragma unroll
        for (int kc2 = 0; kc2 < 2; kc2++){
            const int k0v = wn * 32 + kc2 * 16;
            #pragma unroll
            for (int p = 0; p < 4; p++){
                uint32_t va = stk + 2 * AKTILE + ((p * 16 + b_r) * ASA + k0v + b_c) * 2;
                uint32_t vh4[4], vl4[4];
                ldsm4(va, vh4);
                ldsm4(va + AKTILE, vl4);
                #pragma unroll
                for (int mt = 0; mt < 2; mt++){
                    mma_bf16(O[mt][2*p],   pha[mt][kc2], vh4[0], vh4[1]);
                    mma_bf16(O[mt][2*p],   pha[mt][kc2], vl4[0], vl4[1]);
                    mma_bf16(O[mt][2*p],   pla[mt][kc2], vh4[0], vh4[1]);
                    mma_bf16(O[mt][2*p+1], pha[mt][kc2], vh4[2], vh4[3]);
                    mma_bf16(O[mt][2*p+1], pha[mt][kc2], vl4[2], vl4[3]);
                    mma_bf16(O[mt][2*p+1], pla[mt][kc2], vh4[2], vh4[3]);
                }
            }
        }
    }

    // ---- merge wn partials, normalize, write MH hi/lo ----
    __syncthreads();
    float* exO = (float*)smem;                     // [128][66]
    float* exL = (float*)(smem + 128 * 66 * 4);    // [128]
    if (wn == 1){
        #pragma unroll
        for (int mt = 0; mt < 2; mt++){
            #pragma unroll
            for (int hf = 0; hf < 2; hf++){
                int row = wm * 32 + mt * 16 + hf * 8 + r;
                #pragma unroll
                for (int nt = 0; nt < 8; nt++){
                    exO[row * 66 + nt * 8 + c2]     = O[mt][nt][hf*2];
                    exO[row * 66 + nt * 8 + c2 + 1] = O[mt][nt][hf*2+1];
                }
                if ((lane & 3) == 0) exL[row] = l_i[mt][hf];
            }
        }
    }
    __syncthreads();
    if (wn == 0){
        uint32_t* MHH = (uint32_t*)g_MHhi4;
        uint32_t* MHL = (uint32_t*)g_MHlo4;
        #pragma unroll
        for (int mt = 0; mt < 2; mt++){
            #pragma unroll
            for (int hf = 0; hf < 2; hf++){
                int row = wm * 32 + mt * 16 + hf * 8 + r;
                float linv = 1.f / (l_i[mt][hf] + exL[row]);
                size_t t = (size_t)b * SEQ + qt * 128 + row;
                #pragma unroll
                for (int nt = 0; nt < 8; nt++){
                    float v0 = (O[mt][nt][hf*2]   + exO[row * 66 + nt * 8 + c2])     * linv;
                    float v1 = (O[mt][nt][hf*2+1] + exO[row * 66 + nt * 8 + c2 + 1]) * linv;
                    uint32_t hi, lo;
                    pack_hilo(v0, v1, hi, lo);
                    size_t col = h * 64 + nt * 8 + c2;
                    MHH[(t * DM + col) >> 1] = hi;
                    MHL[(t * DM + col) >> 1] = lo;
                }
            }
        }
    }
}

// ---------------------------------------------------------------------------
extern "C" void kernel_launch(void* const* d_in, const int* in_sizes, int n_in,
                              void* d_out, int out_size)
{
    const float* residual = (const float*)d_in[0];
    const float* W_Q = (const float*)d_in[1];
    const float* W_K = (const float*)d_in[2];
    const float* W_V = (const float*)d_in[3];
    const float* W_O = (const float*)d_in[4];
    float* out = (float*)d_out;

    cudaFuncSetAttribute(gemm_qkv,   cudaFuncAttributeMaxDynamicSharedMemorySize, GEMM_SMEM);
    cudaFuncSetAttribute(gemm_oproj, cudaFuncAttributeMaxDynamicSharedMemorySize, GEMM_SMEM);
    cudaFuncSetAttribute(attn_kernel, cudaFuncAttributeMaxDynamicSharedMemorySize, ATTN_SMEM);

    prep_x<<<TOK * DM / (256 * 8), 256>>>(residual);
    prep_wqkv<<<dim3(3 * NH, 12), 256>>>(W_Q, W_K, W_V);
    prep_wo<<<dim3(12, 12), 256>>>(W_O);

    gemm_qkv<<<dim3(64, 18), 256, GEMM_SMEM>>>();
    attn_kernel<<<dim3(16, BATCH * NH), 256, ATTN_SMEM>>>();
    gemm_oproj<<<dim3(64, 6), 256, GEMM_SMEM>>>(out);
}

// round 8
// speedup vs baseline: 6.4899x; 1.4093x over previous
#include <cuda_runtime.h>
#include <cuda_fp16.h>
#include <cstdint>

#define BATCH 4
#define SEQ   2048
#define DM    768
#define NH    12
#define TOK   (BATCH*SEQ)   // 8192

// ---------------------------------------------------------------------------
// Scratch (uint4 for guaranteed 16B alignment; elements are fp16)
// ---------------------------------------------------------------------------
__device__ uint4 g_Xhi4 [(size_t)TOK*DM/8],  g_Xlo4 [(size_t)TOK*DM/8];
__device__ uint4 g_Wthi4[(size_t)3*NH*64*DM/8], g_Wtlo4[(size_t)3*NH*64*DM/8]; // [mat*NH+h][n][m]
__device__ uint4 g_WOt4[(size_t)DM*DM/8];                                      // [d][n] single
__device__ uint4 g_Qhi4 [(size_t)TOK*DM/8], g_Qlo4 [(size_t)TOK*DM/8];  // [b,h,s,d]
__device__ uint4 g_Khi4 [(size_t)TOK*DM/8], g_Klo4 [(size_t)TOK*DM/8];  // [b,h,s,d]
__device__ uint4 g_Vt4  [(size_t)TOK*DM/8];                             // [b,h,d,s] single
__device__ uint4 g_MHhi4[(size_t)TOK*DM/8], g_MHlo4[(size_t)TOK*DM/8];  // [t, h*64+v]

#define HF(p) ((__half*)(p))

// ---------------------------------------------------------------------------
// Helpers
// ---------------------------------------------------------------------------
__device__ __forceinline__ uint32_t smem_u32(const void* p){
    uint32_t a;
    asm("{ .reg .u64 t; cvta.to.shared.u64 t, %1; cvt.u32.u64 %0, t; }" : "=r"(a) : "l"(p));
    return a;
}
__device__ __forceinline__ void mma_f16(float* d, const uint32_t* a,
                                        uint32_t b0, uint32_t b1){
    asm volatile("mma.sync.aligned.m16n8k16.row.col.f32.f16.f16.f32 "
        "{%0,%1,%2,%3}, {%4,%5,%6,%7}, {%8,%9}, {%0,%1,%2,%3};"
        : "+f"(d[0]), "+f"(d[1]), "+f"(d[2]), "+f"(d[3])
        : "r"(a[0]), "r"(a[1]), "r"(a[2]), "r"(a[3]), "r"(b0), "r"(b1));
}
__device__ __forceinline__ void ldsm4(uint32_t addr, uint32_t* r){
    asm volatile("ldmatrix.sync.aligned.m8n8.x4.shared.b16 {%0,%1,%2,%3}, [%4];"
        : "=r"(r[0]), "=r"(r[1]), "=r"(r[2]), "=r"(r[3]) : "r"(addr));
}
__device__ __forceinline__ void cpa16(uint32_t saddr, const void* g){
    asm volatile("cp.async.cg.shared.global [%0], [%1], 16;" :: "r"(saddr), "l"(g));
}
#define CP_COMMIT() asm volatile("cp.async.commit_group;" ::: "memory")
#define CP_WAIT0()  asm volatile("cp.async.wait_group 0;" ::: "memory")

__device__ __forceinline__ uint32_t pack2(float v0, float v1){
    __half2 h = __floats2half2_rn(v0, v1);
    return *(uint32_t*)&h;
}
__device__ __forceinline__ void pack_hilo(float v0, float v1, uint32_t& hi, uint32_t& lo){
    __half2 hp = __floats2half2_rn(v0, v1);
    float l0 = v0 - __half2float(__low2half(hp));
    float l1 = v1 - __half2float(__high2half(hp));
    __half2 lp = __floats2half2_rn(l0, l1);
    hi = *(uint32_t*)&hp; lo = *(uint32_t*)&lp;
}
__device__ __forceinline__ float exp2a(float t){
    float r;
    asm("ex2.approx.ftz.f32 %0, %1;" : "=f"(r) : "f"(t));
    return r;
}

// ---------------------------------------------------------------------------
// Prep: fp32 -> fp16 hi/lo (+ weight transposes)
// ---------------------------------------------------------------------------
__global__ __launch_bounds__(256) void prep_x(const float* __restrict__ X){
    int i0 = (blockIdx.x * 256 + threadIdx.x) * 8;
    #pragma unroll
    for (int k = 0; k < 8; k++){
        int i = i0 + k;
        float v = X[i];
        __half h = __float2half_rn(v);
        HF(g_Xhi4)[i] = h;
        HF(g_Xlo4)[i] = __float2half_rn(v - __half2float(h));
    }
}

__global__ __launch_bounds__(256) void prep_wqkv(const float* __restrict__ WQ,
                                                 const float* __restrict__ WK,
                                                 const float* __restrict__ WV){
    __shared__ float tile[64][65];
    int x = blockIdx.x;               // mat*12 + h
    int mt = blockIdx.y;              // m tile (12)
    int mat = x / NH, h = x % NH;
    const float* src = (mat == 0 ? WQ : mat == 1 ? WK : WV) + (size_t)h * DM * 64;
    int tid = threadIdx.x;
    #pragma unroll
    for (int i = 0; i < 16; i++){
        int idx = tid + i * 256;
        int r = idx >> 6, c = idx & 63;
        tile[r][c] = src[(size_t)(mt * 64 + r) * 64 + c];
    }
    __syncthreads();
    #pragma unroll
    for (int i = 0; i < 16; i++){
        int idx = tid + i * 256;
        int n = idx >> 6, mc = idx & 63;
        float v = tile[mc][n];
        __half hh = __float2half_rn(v);
        size_t o = ((size_t)x * 64 + n) * DM + mt * 64 + mc;
        HF(g_Wthi4)[o] = hh;
        HF(g_Wtlo4)[o] = __float2half_rn(v - __half2float(hh));
    }
}

__global__ __launch_bounds__(256) void prep_wo(const float* __restrict__ WO){
    __shared__ float tile[64][65];
    int nt = blockIdx.x, dt = blockIdx.y;
    int tid = threadIdx.x;
    #pragma unroll
    for (int i = 0; i < 16; i++){
        int idx = tid + i * 256;
        int r = idx >> 6, c = idx & 63;
        tile[r][c] = WO[(size_t)(nt * 64 + r) * DM + dt * 64 + c];
    }
    __syncthreads();
    #pragma unroll
    for (int i = 0; i < 16; i++){
        int idx = tid + i * 256;
        int dr = idx >> 6, nc = idx & 63;
        size_t o = (size_t)(dt * 64 + dr) * DM + nt * 64 + nc;
        HF(g_WOt4)[o] = __float2half_rn(tile[nc][dr]);
    }
}

// ---------------------------------------------------------------------------
// GEMM: 128x128 tile, K chunks of 32, 8 warps (4m x 2n), cp.async 2-stage,
// ldmatrix fragments. Tiles/stage: Ah,Al,Bh[,Bl]; each 128x40hw = 10240B.
// THREE=true: 3-term (Ah*Bh + Ah*Bl + Al*Bh). false: 2-term (Ah*B + Al*B).
// ---------------------------------------------------------------------------
#define GSA 40
#define GTILE 10240
#define GEMM_SMEM (2*4*GTILE)   // 81920 (max, 3-term case)

template<bool THREE>
__device__ __forceinline__ void gemm_cpa_chunk(
    const __half* GA_h, const __half* GA_l,
    const __half* GB_h, const __half* GB_l,
    int arow0, int brow0, int ch, uint32_t sdst, int lrow, int lh)
{
    size_t ga = (size_t)(arow0 + lrow) * DM + ch * 32 + lh * 16;
    size_t gb = (size_t)(brow0 + lrow) * DM + ch * 32 + lh * 16;
    uint32_t so = (uint32_t)((lrow * GSA + lh * 16) * 2);
    cpa16(sdst           + so, GA_h + ga); cpa16(sdst           + so + 16, GA_h + ga + 8);
    cpa16(sdst +   GTILE + so, GA_l + ga); cpa16(sdst +   GTILE + so + 16, GA_l + ga + 8);
    cpa16(sdst + 2*GTILE + so, GB_h + gb); cpa16(sdst + 2*GTILE + so + 16, GB_h + gb + 8);
    if (THREE){
        cpa16(sdst + 3*GTILE + so, GB_l + gb); cpa16(sdst + 3*GTILE + so + 16, GB_l + gb + 8);
    }
}

template<bool THREE>
__device__ __forceinline__ void gemm_core(
    const __half* GA_h, const __half* GA_l,
    const __half* GB_h, const __half* GB_l,
    int arow0, int brow0, uint32_t sb,
    int tid, int wm, int wn, int lane,
    float acc[2][8][4])
{
    const int STG = (THREE ? 4 : 3) * GTILE;
    const int lrow = tid >> 1, lh = tid & 1;
    const int a_r = lane & 15, a_c = (lane & 16) >> 1;
    const int b_r = (lane & 7) + ((lane & 16) >> 1), b_c = lane & 8;

    gemm_cpa_chunk<THREE>(GA_h, GA_l, GB_h, GB_l, arow0, brow0, 0, sb, lrow, lh);
    CP_COMMIT();

    for (int ch = 0; ch < 24; ch++){
        CP_WAIT0();
        __syncthreads();
        if (ch + 1 < 24){
            gemm_cpa_chunk<THREE>(GA_h, GA_l, GB_h, GB_l, arow0, brow0, ch + 1,
                                  sb + ((ch + 1) & 1) * STG, lrow, lh);
            CP_COMMIT();
        }
        const uint32_t st = sb + (ch & 1) * STG;
        #pragma unroll
        for (int k0 = 0; k0 < 32; k0 += 16){
            uint32_t ah[2][4], al[2][4];
            #pragma unroll
            for (int mt = 0; mt < 2; mt++){
                uint32_t ad = st + ((wm * 32 + mt * 16 + a_r) * GSA + k0 + a_c) * 2;
                ldsm4(ad, ah[mt]);
                ldsm4(ad + GTILE, al[mt]);
            }
            #pragma unroll
            for (int p = 0; p < 4; p++){
                uint32_t bd = st + 2 * GTILE +
                              ((wn * 64 + p * 16 + b_r) * GSA + k0 + b_c) * 2;
                uint32_t bh4[4];
                ldsm4(bd, bh4);
                if (THREE){
                    uint32_t bl4[4];
                    ldsm4(bd + GTILE, bl4);
                    #pragma unroll
                    for (int mt = 0; mt < 2; mt++){
                        mma_f16(acc[mt][2*p],   ah[mt], bh4[0], bh4[1]);
                        mma_f16(acc[mt][2*p],   ah[mt], bl4[0], bl4[1]);
                        mma_f16(acc[mt][2*p],   al[mt], bh4[0], bh4[1]);
                        mma_f16(acc[mt][2*p+1], ah[mt], bh4[2], bh4[3]);
                        mma_f16(acc[mt][2*p+1], ah[mt], bl4[2], bl4[3]);
                        mma_f16(acc[mt][2*p+1], al[mt], bh4[2], bh4[3]);
                    }
                } else {
                    #pragma unroll
                    for (int mt = 0; mt < 2; mt++){
                        mma_f16(acc[mt][2*p],   ah[mt], bh4[0], bh4[1]);
                        mma_f16(acc[mt][2*p],   al[mt], bh4[0], bh4[1]);
                        mma_f16(acc[mt][2*p+1], ah[mt], bh4[2], bh4[3]);
                        mma_f16(acc[mt][2*p+1], al[mt], bh4[2], bh4[3]);
                    }
                }
            }
        }
    }
}

// QKV projection: A = X[t, m], B = Wt rows. Q,K: 3-term. V: 2-term, single out.
__global__ __launch_bounds__(256, 2) void gemm_qkv(){
    extern __shared__ __align__(16) char smem[];
    const uint32_t sb = smem_u32(smem);
    const int tid = threadIdx.x, w = tid >> 5, lane = tid & 31;
    const int wm = w & 3, wn = w >> 2;
    const int r = lane >> 2, c2 = (lane & 3) * 2;
    const int t0 = blockIdx.x * 128;
    const int j = blockIdx.y;
    const int mat = j / 6, h0 = (j % 6) * 2;
    const int brow0 = (mat * NH + h0) * 64;

    float acc[2][8][4] = {};
    if (mat < 2)
        gemm_core<true >(HF(g_Xhi4), HF(g_Xlo4), HF(g_Wthi4), HF(g_Wtlo4),
                         t0, brow0, sb, tid, wm, wn, lane, acc);
    else
        gemm_core<false>(HF(g_Xhi4), HF(g_Xlo4), HF(g_Wthi4), HF(g_Wtlo4),
                         t0, brow0, sb, tid, wm, wn, lane, acc);

    const int hh_g = h0 + wn;
    #pragma unroll
    for (int mt = 0; mt < 2; mt++){
        #pragma unroll
        for (int hf = 0; hf < 2; hf++){
            int srow = t0 + wm * 32 + mt * 16 + r + hf * 8;
            int bb = srow >> 11, s = srow & 2047;
            if (mat < 2){
                uint32_t* DH = (uint32_t*)(mat == 0 ? g_Qhi4 : g_Khi4);
                uint32_t* DL = (uint32_t*)(mat == 0 ? g_Qlo4 : g_Klo4);
                size_t base = ((size_t)(bb * NH + hh_g) * SEQ + s) * 32;
                #pragma unroll
                for (int nt = 0; nt < 8; nt++){
                    int d = nt * 8 + c2;
                    uint32_t hi, lo;
                    pack_hilo(acc[mt][nt][hf*2], acc[mt][nt][hf*2+1], hi, lo);
                    DH[base + (d >> 1)] = hi;
                    DL[base + (d >> 1)] = lo;
                }
            } else {
                __half* VT = HF(g_Vt4);
                #pragma unroll
                for (int nt = 0; nt < 8; nt++){
                    #pragma unroll
                    for (int j2 = 0; j2 < 2; j2++){
                        int d = nt * 8 + c2 + j2;
                        size_t o = ((size_t)(bb * NH + hh_g) * 64 + d) * SEQ + s;
                        VT[o] = __float2half_rn(acc[mt][nt][hf*2+j2]);
                    }
                }
            }
        }
    }
}

// Output projection (2-term: MHh*WO + MHl*WO)
__global__ __launch_bounds__(256, 2) void gemm_oproj(float* __restrict__ out){
    extern __shared__ __align__(16) char smem[];
    const uint32_t sb = smem_u32(smem);
    const int tid = threadIdx.x, w = tid >> 5, lane = tid & 31;
    const int wm = w & 3, wn = w >> 2;
    const int r = lane >> 2, c2 = (lane & 3) * 2;
    const int t0 = blockIdx.x * 128;
    const int d0 = blockIdx.y * 128;

    float acc[2][8][4] = {};
    gemm_core<false>(HF(g_MHhi4), HF(g_MHlo4), HF(g_WOt4), HF(g_WOt4),
                     t0, d0, sb, tid, wm, wn, lane, acc);

    #pragma unroll
    for (int mt = 0; mt < 2; mt++){
        #pragma unroll
        for (int hf = 0; hf < 2; hf++){
            int srow = t0 + wm * 32 + mt * 16 + r + hf * 8;
            #pragma unroll
            for (int nt = 0; nt < 8; nt++){
                int dcol = d0 + wn * 64 + nt * 8 + c2;
                float2 v = make_float2(acc[mt][nt][hf*2], acc[mt][nt][hf*2+1]);
                *(float2*)(out + (size_t)srow * DM + dcol) = v;
            }
        }
    }
}

// ---------------------------------------------------------------------------
// Flash attention: 128-q tile, 64-kv tile, 8 warps (4m x 2n)
// S: 3-term (Qh/Ql x Kh/Kl). P single fp16, V single fp16 -> PV 1-term.
// K hi/lo + V single double-buffered. smem 93184B; 2 CTAs/SM.
//   Q: hi 0, lo 18432 | KV stages at 36864 (+s*27648): Kh 0, Kl 9216, V 18432
//   redmax at 92160
// ---------------------------------------------------------------------------
#define ASA    72
#define AQTILE 18432
#define AKTILE 9216
#define AT_KV  36864
#define AKVSTG (3*AKTILE)       // 27648
#define AT_RED 92160
#define ATTN_SMEM (AT_RED + 2*128*4)   // 93184

__device__ __forceinline__ void attn_cpa_kv(
    const __half* KH, const __half* KL, const __half* VT,
    int bh_idx, int jj, uint32_t sdst, int lrow, int lq)
{
    size_t gk = ((size_t)bh_idx * SEQ + jj * 64 + lrow) * 64 + lq * 16;
    size_t gv = ((size_t)(bh_idx * 64 + lrow)) * SEQ + jj * 64 + lq * 16;
    uint32_t so = (uint32_t)((lrow * ASA + lq * 16) * 2);
    cpa16(sdst            + so, KH + gk); cpa16(sdst            + so + 16, KH + gk + 8);
    cpa16(sdst +   AKTILE + so, KL + gk); cpa16(sdst +   AKTILE + so + 16, KL + gk + 8);
    cpa16(sdst + 2*AKTILE + so, VT + gv); cpa16(sdst + 2*AKTILE + so + 16, VT + gv + 8);
}

__global__ __launch_bounds__(256, 2) void attn_kernel(){
    extern __shared__ __align__(16) char smem[];
    const uint32_t sb = smem_u32(smem);
    float* redmax = (float*)(smem + AT_RED);

    const int tid = threadIdx.x, w = tid >> 5, lane = tid & 31;
    const int wm = w & 3, wn = w >> 2;
    const int r = lane >> 2, c2 = (lane & 3) * 2;
    const int a_r = lane & 15, a_c = (lane & 16) >> 1;
    const int b_r = (lane & 7) + ((lane & 16) >> 1), b_c = lane & 8;

    const int qt = 15 - blockIdx.x;   // heavy tiles first
    const int pr = blockIdx.y;
    const int b = pr / NH, h = pr % NH;
    const int bh_idx = b * NH + h;
    const int jmax = 2 * qt + 1;

    const __half* QH = HF(g_Qhi4);
    const __half* QL = HF(g_Qlo4);
    const __half* KH = HF(g_Khi4);
    const __half* KL = HF(g_Klo4);
    const __half* VT = HF(g_Vt4);

    const int lrowQ = tid >> 1, lhQ = tid & 1;
    const int lrowK = tid >> 2, lqK = tid & 3;

    // prologue: Q + KV stage 0
    {
        size_t gq = ((size_t)bh_idx * SEQ + qt * 128 + lrowQ) * 64 + lhQ * 32;
        uint32_t so = (uint32_t)((lrowQ * ASA + lhQ * 32) * 2);
        #pragma unroll
        for (int i = 0; i < 4; i++){
            cpa16(sb          + so + i * 16, QH + gq + i * 8);
            cpa16(sb + AQTILE + so + i * 16, QL + gq + i * 8);
        }
        attn_cpa_kv(KH, KL, VT, bh_idx, 0, sb + AT_KV, lrowK, lqK);
        CP_COMMIT();
    }

    float O[2][8][4] = {};
    float m_i[2][2] = {{-1e30f, -1e30f}, {-1e30f, -1e30f}};
    float l_i[2][2] = {};
    const float CSC = 0.125f * 1.4426950408889634f;  // scale * log2(e)

    for (int jj = 0; jj <= jmax; jj++){
        CP_WAIT0();
        __syncthreads();
        if (jj + 1 <= jmax){
            attn_cpa_kv(KH, KL, VT, bh_idx, jj + 1,
                        sb + AT_KV + ((jj + 1) & 1) * AKVSTG, lrowK, lqK);
            CP_COMMIT();
        }
        const uint32_t stk = sb + AT_KV + (jj & 1) * AKVSTG;

        // ---- S = Q K^T (3-term) ----
        float sacc[2][4][4] = {};
        #pragma unroll
        for (int kc = 0; kc < 4; kc++){
            const int k0 = kc * 16;
            uint32_t qh4[2][4], ql4[2][4];
            #pragma unroll
            for (int mt = 0; mt < 2; mt++){
                uint32_t qa = sb + ((wm * 32 + mt * 16 + a_r) * ASA + k0 + a_c) * 2;
                ldsm4(qa, qh4[mt]);
                ldsm4(qa + AQTILE, ql4[mt]);
            }
            #pragma unroll
            for (int p = 0; p < 2; p++){
                uint32_t ka = stk + ((wn * 32 + p * 16 + b_r) * ASA + k0 + b_c) * 2;
                uint32_t kh4[4], kl4[4];
                ldsm4(ka, kh4);
                ldsm4(ka + AKTILE, kl4);
                #pragma unroll
                for (int mt = 0; mt < 2; mt++){
                    mma_f16(sacc[mt][2*p],   qh4[mt], kh4[0], kh4[1]);
                    mma_f16(sacc[mt][2*p],   qh4[mt], kl4[0], kl4[1]);
                    mma_f16(sacc[mt][2*p],   ql4[mt], kh4[0], kh4[1]);
                    mma_f16(sacc[mt][2*p+1], qh4[mt], kh4[2], kh4[3]);
                    mma_f16(sacc[mt][2*p+1], qh4[mt], kl4[2], kl4[3]);
                    mma_f16(sacc[mt][2*p+1], ql4[mt], kh4[2], kh4[3]);
                }
            }
        }

        // ---- scale (+ causal mask only on diagonal tiles) + row max ----
        const bool domask = (jj >= 2 * qt);
        #pragma unroll
        for (int mt = 0; mt < 2; mt++){
            #pragma unroll
            for (int hf = 0; hf < 2; hf++){
                int row = wm * 32 + mt * 16 + hf * 8 + r;
                float mx = -1e30f;
                if (domask){
                    int qrow = qt * 128 + row;
                    #pragma unroll
                    for (int nt = 0; nt < 4; nt++){
                        #pragma unroll
                        for (int j2 = 0; j2 < 2; j2++){
                            int col = jj * 64 + wn * 32 + nt * 8 + c2 + j2;
                            float v = sacc[mt][nt][hf*2+j2] * CSC;
                            if (col > qrow) v = -1e30f;
                            sacc[mt][nt][hf*2+j2] = v;
                            mx = fmaxf(mx, v);
                        }
                    }
                } else {
                    #pragma unroll
                    for (int nt = 0; nt < 4; nt++){
                        #pragma unroll
                        for (int j2 = 0; j2 < 2; j2++){
                            float v = sacc[mt][nt][hf*2+j2] * CSC;
                            sacc[mt][nt][hf*2+j2] = v;
                            mx = fmaxf(mx, v);
                        }
                    }
                }
                mx = fmaxf(mx, __shfl_xor_sync(0xffffffffu, mx, 1));
                mx = fmaxf(mx, __shfl_xor_sync(0xffffffffu, mx, 2));
                if ((lane & 3) == 0) redmax[wn * 128 + row] = mx;
            }
        }
        __syncthreads();

        // ---- softmax: exp (MUFU), per-warp l partial, O rescale ----
        #pragma unroll
        for (int mt = 0; mt < 2; mt++){
            #pragma unroll
            for (int hf = 0; hf < 2; hf++){
                int row = wm * 32 + mt * 16 + hf * 8 + r;
                float mn = fmaxf(m_i[mt][hf], fmaxf(redmax[row], redmax[128 + row]));
                float alpha = exp2a(m_i[mt][hf] - mn);
                m_i[mt][hf] = mn;
                float rs = 0.f;
                #pragma unroll
                for (int nt = 0; nt < 4; nt++){
                    #pragma unroll
                    for (int j2 = 0; j2 < 2; j2++){
                        float p = exp2a(sacc[mt][nt][hf*2+j2] - mn);
                        sacc[mt][nt][hf*2+j2] = p;
                        rs += p;
                    }
                }
                rs += __shfl_xor_sync(0xffffffffu, rs, 1);
                rs += __shfl_xor_sync(0xffffffffu, rs, 2);
                l_i[mt][hf] = l_i[mt][hf] * alpha + rs;
                #pragma unroll
                for (int nt = 0; nt < 8; nt++){
                    O[mt][nt][hf*2]   *= alpha;
                    O[mt][nt][hf*2+1] *= alpha;
                }
            }
        }

        // P fragments (register-only, single fp16): A-frag layout from sacc
        uint32_t pha[2][2][4];
        #pragma unroll
        for (int mt = 0; mt < 2; mt++){
            #pragma unroll
            for (int kc2 = 0; kc2 < 2; kc2++){
                pha[mt][kc2][0] = pack2(sacc[mt][2*kc2][0],   sacc[mt][2*kc2][1]);
                pha[mt][kc2][1] = pack2(sacc[mt][2*kc2][2],   sacc[mt][2*kc2][3]);
                pha[mt][kc2][2] = pack2(sacc[mt][2*kc2+1][0], sacc[mt][2*kc2+1][1]);
                pha[mt][kc2][3] = pack2(sacc[mt][2*kc2+1][2], sacc[mt][2*kc2+1][3]);
            }
        }

        // ---- PV (1-term): O partial over this warp's 32-kv slice ----
        #pragma unroll
        for (int kc2 = 0; kc2 < 2; kc2++){
            const int k0v = wn * 32 + kc2 * 16;
            #pragma unroll
            for (int p = 0; p < 4; p++){
                uint32_t va = stk + 2 * AKTILE + ((p * 16 + b_r) * ASA + k0v + b_c) * 2;
                uint32_t vh4[4];
                ldsm4(va, vh4);
                #pragma unroll
                for (int mt = 0; mt < 2; mt++){
                    mma_f16(O[mt][2*p],   pha[mt][kc2], vh4[0], vh4[1]);
                    mma_f16(O[mt][2*p+1], pha[mt][kc2], vh4[2], vh4[3]);
                }
            }
        }
    }

    // ---- merge wn partials, normalize, write MH hi/lo ----
    __syncthreads();
    float* exO = (float*)smem;                     // [128][66]
    float* exL = (float*)(smem + 128 * 66 * 4);    // [128]
    if (wn == 1){
        #pragma unroll
        for (int mt = 0; mt < 2; mt++){
            #pragma unroll
            for (int hf = 0; hf < 2; hf++){
                int row = wm * 32 + mt * 16 + hf * 8 + r;
                #pragma unroll
                for (int nt = 0; nt < 8; nt++){
                    exO[row * 66 + nt * 8 + c2]     = O[mt][nt][hf*2];
                    exO[row * 66 + nt * 8 + c2 + 1] = O[mt][nt][hf*2+1];
                }
                if ((lane & 3) == 0) exL[row] = l_i[mt][hf];
            }
        }
    }
    __syncthreads();
    if (wn == 0){
        uint32_t* MHH = (uint32_t*)g_MHhi4;
        uint32_t* MHL = (uint32_t*)g_MHlo4;
        #pragma unroll
        for (int mt = 0; mt < 2; mt++){
            #pragma unroll
            for (int hf = 0; hf < 2; hf++){
                int row = wm * 32 + mt * 16 + hf * 8 + r;
                float linv = 1.f / (l_i[mt][hf] + exL[row]);
                size_t t = (size_t)b * SEQ + qt * 128 + row;
                #pragma unroll
                for (int nt = 0; nt < 8; nt++){
                    float v0 = (O[mt][nt][hf*2]   + exO[row * 66 + nt * 8 + c2])     * linv;
                    float v1 = (O[mt][nt][hf*2+1] + exO[row * 66 + nt * 8 + c2 + 1]) * linv;
                    uint32_t hi, lo;
                    pack_hilo(v0, v1, hi, lo);
                    size_t col = h * 64 + nt * 8 + c2;
                    MHH[(t * DM + col) >> 1] = hi;
                    MHL[(t * DM + col) >> 1] = lo;
                }
            }
        }
    }
}

// ---------------------------------------------------------------------------
extern "C" void kernel_launch(void* const* d_in, const int* in_sizes, int n_in,
                              void* d_out, int out_size)
{
    const float* residual = (const float*)d_in[0];
    const float* W_Q = (const float*)d_in[1];
    const float* W_K = (const float*)d_in[2];
    const float* W_V = (const float*)d_in[3];
    const float* W_O = (const float*)d_in[4];
    float* out = (float*)d_out;

    cudaFuncSetAttribute(gemm_qkv,   cudaFuncAttributeMaxDynamicSharedMemorySize, GEMM_SMEM);
    cudaFuncSetAttribute(gemm_oproj, cudaFuncAttributeMaxDynamicSharedMemorySize, GEMM_SMEM);
    cudaFuncSetAttribute(attn_kernel, cudaFuncAttributeMaxDynamicSharedMemorySize, ATTN_SMEM);

    prep_x<<<TOK * DM / (256 * 8), 256>>>(residual);
    prep_wqkv<<<dim3(3 * NH, 12), 256>>>(W_Q, W_K, W_V);
    prep_wo<<<dim3(12, 12), 256>>>(W_O);

    gemm_qkv<<<dim3(64, 18), 256, GEMM_SMEM>>>();
    attn_kernel<<<dim3(16, BATCH * NH), 256, ATTN_SMEM>>>();
    gemm_oproj<<<dim3(64, 6), 256, 2*3*GTILE>>>(out);
}

// round 9
// speedup vs baseline: 6.7473x; 1.0397x over previous
#include <cuda_runtime.h>
#include <cuda_fp16.h>
#include <cstdint>

#define BATCH 4
#define SEQ   2048
#define DM    768
#define NH    12
#define TOK   (BATCH*SEQ)   // 8192

// ---------------------------------------------------------------------------
// Scratch (uint4 for guaranteed 16B alignment; elements are fp16)
// ---------------------------------------------------------------------------
__device__ uint4 g_Xhi4 [(size_t)TOK*DM/8],  g_Xlo4 [(size_t)TOK*DM/8];
__device__ uint4 g_Wthi4[(size_t)3*NH*64*DM/8], g_Wtlo4[(size_t)3*NH*64*DM/8]; // [mat*NH+h][n][m]
__device__ uint4 g_WOt4[(size_t)DM*DM/8];                                      // [d][n] single
__device__ uint4 g_Qhi4 [(size_t)TOK*DM/8], g_Qlo4 [(size_t)TOK*DM/8];  // [b,h,s,d]
__device__ uint4 g_Khi4 [(size_t)TOK*DM/8], g_Klo4 [(size_t)TOK*DM/8];  // [b,h,s,d]
__device__ uint4 g_Vt4  [(size_t)TOK*DM/8];                             // [b,h,d,s] single
__device__ uint4 g_MHhi4[(size_t)TOK*DM/8], g_MHlo4[(size_t)TOK*DM/8];  // [t, h*64+v]

#define HF(p) ((__half*)(p))

// ---------------------------------------------------------------------------
// Helpers
// ---------------------------------------------------------------------------
__device__ __forceinline__ uint32_t smem_u32(const void* p){
    uint32_t a;
    asm("{ .reg .u64 t; cvta.to.shared.u64 t, %1; cvt.u32.u64 %0, t; }" : "=r"(a) : "l"(p));
    return a;
}
__device__ __forceinline__ void mma_f16(float* d, const uint32_t* a,
                                        uint32_t b0, uint32_t b1){
    asm volatile("mma.sync.aligned.m16n8k16.row.col.f32.f16.f16.f32 "
        "{%0,%1,%2,%3}, {%4,%5,%6,%7}, {%8,%9}, {%0,%1,%2,%3};"
        : "+f"(d[0]), "+f"(d[1]), "+f"(d[2]), "+f"(d[3])
        : "r"(a[0]), "r"(a[1]), "r"(a[2]), "r"(a[3]), "r"(b0), "r"(b1));
}
__device__ __forceinline__ void ldsm4(uint32_t addr, uint32_t* r){
    asm volatile("ldmatrix.sync.aligned.m8n8.x4.shared.b16 {%0,%1,%2,%3}, [%4];"
        : "=r"(r[0]), "=r"(r[1]), "=r"(r[2]), "=r"(r[3]) : "r"(addr));
}
__device__ __forceinline__ void cpa16(uint32_t saddr, const void* g){
    asm volatile("cp.async.cg.shared.global [%0], [%1], 16;" :: "r"(saddr), "l"(g));
}
#define CP_COMMIT() asm volatile("cp.async.commit_group;" ::: "memory")
#define CP_WAIT0()  asm volatile("cp.async.wait_group 0;" ::: "memory")

__device__ __forceinline__ uint32_t pack2(float v0, float v1){
    __half2 h = __floats2half2_rn(v0, v1);
    return *(uint32_t*)&h;
}
__device__ __forceinline__ void pack_hilo(float v0, float v1, uint32_t& hi, uint32_t& lo){
    __half2 hp = __floats2half2_rn(v0, v1);
    float l0 = v0 - __half2float(__low2half(hp));
    float l1 = v1 - __half2float(__high2half(hp));
    __half2 lp = __floats2half2_rn(l0, l1);
    hi = *(uint32_t*)&hp; lo = *(uint32_t*)&lp;
}
__device__ __forceinline__ float exp2a(float t){
    float r;
    asm("ex2.approx.ftz.f32 %0, %1;" : "=f"(r) : "f"(t));
    return r;
}

// ---------------------------------------------------------------------------
// Prep: fp32 -> fp16 hi/lo (+ weight transposes)
// ---------------------------------------------------------------------------
__global__ __launch_bounds__(256) void prep_x(const float* __restrict__ X){
    int i0 = (blockIdx.x * 256 + threadIdx.x) * 8;
    #pragma unroll
    for (int k = 0; k < 8; k++){
        int i = i0 + k;
        float v = X[i];
        __half h = __float2half_rn(v);
        HF(g_Xhi4)[i] = h;
        HF(g_Xlo4)[i] = __float2half_rn(v - __half2float(h));
    }
}

__global__ __launch_bounds__(256) void prep_wqkv(const float* __restrict__ WQ,
                                                 const float* __restrict__ WK,
                                                 const float* __restrict__ WV){
    __shared__ float tile[64][65];
    int x = blockIdx.x;               // mat*12 + h
    int mt = blockIdx.y;              // m tile (12)
    int mat = x / NH, h = x % NH;
    const float* src = (mat == 0 ? WQ : mat == 1 ? WK : WV) + (size_t)h * DM * 64;
    int tid = threadIdx.x;
    #pragma unroll
    for (int i = 0; i < 16; i++){
        int idx = tid + i * 256;
        int r = idx >> 6, c = idx & 63;
        tile[r][c] = src[(size_t)(mt * 64 + r) * 64 + c];
    }
    __syncthreads();
    #pragma unroll
    for (int i = 0; i < 16; i++){
        int idx = tid + i * 256;
        int n = idx >> 6, mc = idx & 63;
        float v = tile[mc][n];
        __half hh = __float2half_rn(v);
        size_t o = ((size_t)x * 64 + n) * DM + mt * 64 + mc;
        HF(g_Wthi4)[o] = hh;
        HF(g_Wtlo4)[o] = __float2half_rn(v - __half2float(hh));
    }
}

__global__ __launch_bounds__(256) void prep_wo(const float* __restrict__ WO){
    __shared__ float tile[64][65];
    int nt = blockIdx.x, dt = blockIdx.y;
    int tid = threadIdx.x;
    #pragma unroll
    for (int i = 0; i < 16; i++){
        int idx = tid + i * 256;
        int r = idx >> 6, c = idx & 63;
        tile[r][c] = WO[(size_t)(nt * 64 + r) * DM + dt * 64 + c];
    }
    __syncthreads();
    #pragma unroll
    for (int i = 0; i < 16; i++){
        int idx = tid + i * 256;
        int dr = idx >> 6, nc = idx & 63;
        size_t o = (size_t)(dt * 64 + dr) * DM + nt * 64 + nc;
        HF(g_WOt4)[o] = __float2half_rn(tile[nc][dr]);
    }
}

// ---------------------------------------------------------------------------
// GEMM: 128x128 tile, K chunks of 32, 8 warps (4m x 2n), cp.async 2-stage,
// ldmatrix fragments. Tiles/stage: Ah,Al,Bh[,Bl]; each 128x40hw = 10240B.
// ---------------------------------------------------------------------------
#define GSA 40
#define GTILE 10240
#define GEMM_SMEM (2*4*GTILE)   // 81920 (max, 3-term case)

template<bool THREE>
__device__ __forceinline__ void gemm_cpa_chunk(
    const __half* GA_h, const __half* GA_l,
    const __half* GB_h, const __half* GB_l,
    int arow0, int brow0, int ch, uint32_t sdst, int lrow, int lh)
{
    size_t ga = (size_t)(arow0 + lrow) * DM + ch * 32 + lh * 16;
    size_t gb = (size_t)(brow0 + lrow) * DM + ch * 32 + lh * 16;
    uint32_t so = (uint32_t)((lrow * GSA + lh * 16) * 2);
    cpa16(sdst           + so, GA_h + ga); cpa16(sdst           + so + 16, GA_h + ga + 8);
    cpa16(sdst +   GTILE + so, GA_l + ga); cpa16(sdst +   GTILE + so + 16, GA_l + ga + 8);
    cpa16(sdst + 2*GTILE + so, GB_h + gb); cpa16(sdst + 2*GTILE + so + 16, GB_h + gb + 8);
    if (THREE){
        cpa16(sdst + 3*GTILE + so, GB_l + gb); cpa16(sdst + 3*GTILE + so + 16, GB_l + gb + 8);
    }
}

template<bool THREE>
__device__ __forceinline__ void gemm_core(
    const __half* GA_h, const __half* GA_l,
    const __half* GB_h, const __half* GB_l,
    int arow0, int brow0, uint32_t sb,
    int tid, int wm, int wn, int lane,
    float acc[2][8][4])
{
    const int STG = (THREE ? 4 : 3) * GTILE;
    const int lrow = tid >> 1, lh = tid & 1;
    const int a_r = lane & 15, a_c = (lane & 16) >> 1;
    const int b_r = (lane & 7) + ((lane & 16) >> 1), b_c = lane & 8;

    gemm_cpa_chunk<THREE>(GA_h, GA_l, GB_h, GB_l, arow0, brow0, 0, sb, lrow, lh);
    CP_COMMIT();

    for (int ch = 0; ch < 24; ch++){
        CP_WAIT0();
        __syncthreads();
        if (ch + 1 < 24){
            gemm_cpa_chunk<THREE>(GA_h, GA_l, GB_h, GB_l, arow0, brow0, ch + 1,
                                  sb + ((ch + 1) & 1) * STG, lrow, lh);
            CP_COMMIT();
        }
        const uint32_t st = sb + (ch & 1) * STG;
        #pragma unroll
        for (int k0 = 0; k0 < 32; k0 += 16){
            uint32_t ah[2][4], al[2][4];
            #pragma unroll
            for (int mt = 0; mt < 2; mt++){
                uint32_t ad = st + ((wm * 32 + mt * 16 + a_r) * GSA + k0 + a_c) * 2;
                ldsm4(ad, ah[mt]);
                ldsm4(ad + GTILE, al[mt]);
            }
            #pragma unroll
            for (int p = 0; p < 4; p++){
                uint32_t bd = st + 2 * GTILE +
                              ((wn * 64 + p * 16 + b_r) * GSA + k0 + b_c) * 2;
                uint32_t bh4[4];
                ldsm4(bd, bh4);
                if (THREE){
                    uint32_t bl4[4];
                    ldsm4(bd + GTILE, bl4);
                    #pragma unroll
                    for (int mt = 0; mt < 2; mt++){
                        mma_f16(acc[mt][2*p],   ah[mt], bh4[0], bh4[1]);
                        mma_f16(acc[mt][2*p],   ah[mt], bl4[0], bl4[1]);
                        mma_f16(acc[mt][2*p],   al[mt], bh4[0], bh4[1]);
                        mma_f16(acc[mt][2*p+1], ah[mt], bh4[2], bh4[3]);
                        mma_f16(acc[mt][2*p+1], ah[mt], bl4[2], bl4[3]);
                        mma_f16(acc[mt][2*p+1], al[mt], bh4[2], bh4[3]);
                    }
                } else {
                    #pragma unroll
                    for (int mt = 0; mt < 2; mt++){
                        mma_f16(acc[mt][2*p],   ah[mt], bh4[0], bh4[1]);
                        mma_f16(acc[mt][2*p],   al[mt], bh4[0], bh4[1]);
                        mma_f16(acc[mt][2*p+1], ah[mt], bh4[2], bh4[3]);
                        mma_f16(acc[mt][2*p+1], al[mt], bh4[2], bh4[3]);
                    }
                }
            }
        }
    }
}

// QKV projection: A = X[t, m], B = Wt rows. Q,K: 3-term. V: 2-term, single out.
__global__ __launch_bounds__(256, 2) void gemm_qkv(){
    extern __shared__ __align__(16) char smem[];
    const uint32_t sb = smem_u32(smem);
    const int tid = threadIdx.x, w = tid >> 5, lane = tid & 31;
    const int wm = w & 3, wn = w >> 2;
    const int r = lane >> 2, c2 = (lane & 3) * 2;
    const int t0 = blockIdx.x * 128;
    const int j = blockIdx.y;
    const int mat = j / 6, h0 = (j % 6) * 2;
    const int brow0 = (mat * NH + h0) * 64;

    float acc[2][8][4] = {};
    if (mat < 2)
        gemm_core<true >(HF(g_Xhi4), HF(g_Xlo4), HF(g_Wthi4), HF(g_Wtlo4),
                         t0, brow0, sb, tid, wm, wn, lane, acc);
    else
        gemm_core<false>(HF(g_Xhi4), HF(g_Xlo4), HF(g_Wthi4), HF(g_Wtlo4),
                         t0, brow0, sb, tid, wm, wn, lane, acc);

    const int hh_g = h0 + wn;
    #pragma unroll
    for (int mt = 0; mt < 2; mt++){
        #pragma unroll
        for (int hf = 0; hf < 2; hf++){
            int srow = t0 + wm * 32 + mt * 16 + r + hf * 8;
            int bb = srow >> 11, s = srow & 2047;
            if (mat < 2){
                uint32_t* DH = (uint32_t*)(mat == 0 ? g_Qhi4 : g_Khi4);
                uint32_t* DL = (uint32_t*)(mat == 0 ? g_Qlo4 : g_Klo4);
                size_t base = ((size_t)(bb * NH + hh_g) * SEQ + s) * 32;
                #pragma unroll
                for (int nt = 0; nt < 8; nt++){
                    int d = nt * 8 + c2;
                    uint32_t hi, lo;
                    pack_hilo(acc[mt][nt][hf*2], acc[mt][nt][hf*2+1], hi, lo);
                    DH[base + (d >> 1)] = hi;
                    DL[base + (d >> 1)] = lo;
                }
            } else {
                __half* VT = HF(g_Vt4);
                #pragma unroll
                for (int nt = 0; nt < 8; nt++){
                    #pragma unroll
                    for (int j2 = 0; j2 < 2; j2++){
                        int d = nt * 8 + c2 + j2;
                        size_t o = ((size_t)(bb * NH + hh_g) * 64 + d) * SEQ + s;
                        VT[o] = __float2half_rn(acc[mt][nt][hf*2+j2]);
                    }
                }
            }
        }
    }
}

// Output projection (2-term: MHh*WO + MHl*WO)
__global__ __launch_bounds__(256, 2) void gemm_oproj(float* __restrict__ out){
    extern __shared__ __align__(16) char smem[];
    const uint32_t sb = smem_u32(smem);
    const int tid = threadIdx.x, w = tid >> 5, lane = tid & 31;
    const int wm = w & 3, wn = w >> 2;
    const int r = lane >> 2, c2 = (lane & 3) * 2;
    const int t0 = blockIdx.x * 128;
    const int d0 = blockIdx.y * 128;

    float acc[2][8][4] = {};
    gemm_core<false>(HF(g_MHhi4), HF(g_MHlo4), HF(g_WOt4), HF(g_WOt4),
                     t0, d0, sb, tid, wm, wn, lane, acc);

    #pragma unroll
    for (int mt = 0; mt < 2; mt++){
        #pragma unroll
        for (int hf = 0; hf < 2; hf++){
            int srow = t0 + wm * 32 + mt * 16 + r + hf * 8;
            #pragma unroll
            for (int nt = 0; nt < 8; nt++){
                int dcol = d0 + wn * 64 + nt * 8 + c2;
                float2 v = make_float2(acc[mt][nt][hf*2], acc[mt][nt][hf*2+1]);
                *(float2*)(out + (size_t)srow * DM + dcol) = v;
            }
        }
    }
}

// ---------------------------------------------------------------------------
// Flash attention: 128-q tile, 64-kv tile, 8 warps as 8m x 1n:
// each warp owns 16 q rows and ALL 64 kv columns -> softmax reductions are
// quad-shuffles only; no cross-warp exchange, one sync per kv iteration,
// no final merge. S 3-term; P,V single fp16 -> PV 1-term.
//   Q: hi 0, lo 18432 | KV stages at 36864 (+s*27648): Kh 0, Kl 9216, V 18432
// ---------------------------------------------------------------------------
#define ASA    72
#define AQTILE 18432
#define AKTILE 9216
#define AT_KV  36864
#define AKVSTG (3*AKTILE)       // 27648
#define ATTN_SMEM (AT_KV + 2*AKVSTG)   // 92160

__device__ __forceinline__ void attn_cpa_kv(
    const __half* KH, const __half* KL, const __half* VT,
    int bh_idx, int jj, uint32_t sdst, int lrow, int lq)
{
    size_t gk = ((size_t)bh_idx * SEQ + jj * 64 + lrow) * 64 + lq * 16;
    size_t gv = ((size_t)(bh_idx * 64 + lrow)) * SEQ + jj * 64 + lq * 16;
    uint32_t so = (uint32_t)((lrow * ASA + lq * 16) * 2);
    cpa16(sdst            + so, KH + gk); cpa16(sdst            + so + 16, KH + gk + 8);
    cpa16(sdst +   AKTILE + so, KL + gk); cpa16(sdst +   AKTILE + so + 16, KL + gk + 8);
    cpa16(sdst + 2*AKTILE + so, VT + gv); cpa16(sdst + 2*AKTILE + so + 16, VT + gv + 8);
}

__global__ __launch_bounds__(256, 2) void attn_kernel(){
    extern __shared__ __align__(16) char smem[];
    const uint32_t sb = smem_u32(smem);

    const int tid = threadIdx.x, w = tid >> 5, lane = tid & 31;
    const int r = lane >> 2, c2 = (lane & 3) * 2;
    const int a_r = lane & 15, a_c = (lane & 16) >> 1;
    const int b_r = (lane & 7) + ((lane & 16) >> 1), b_c = lane & 8;

    const int qt = 15 - blockIdx.x;   // heavy tiles first
    const int pr = blockIdx.y;
    const int b = pr / NH, h = pr % NH;
    const int bh_idx = b * NH + h;
    const int jmax = 2 * qt + 1;

    const __half* QH = HF(g_Qhi4);
    const __half* QL = HF(g_Qlo4);
    const __half* KH = HF(g_Khi4);
    const __half* KL = HF(g_Klo4);
    const __half* VT = HF(g_Vt4);

    const int lrowQ = tid >> 1, lhQ = tid & 1;
    const int lrowK = tid >> 2, lqK = tid & 3;

    // prologue: Q + KV stage 0
    {
        size_t gq = ((size_t)bh_idx * SEQ + qt * 128 + lrowQ) * 64 + lhQ * 32;
        uint32_t so = (uint32_t)((lrowQ * ASA + lhQ * 32) * 2);
        #pragma unroll
        for (int i = 0; i < 4; i++){
            cpa16(sb          + so + i * 16, QH + gq + i * 8);
            cpa16(sb + AQTILE + so + i * 16, QL + gq + i * 8);
        }
        attn_cpa_kv(KH, KL, VT, bh_idx, 0, sb + AT_KV, lrowK, lqK);
        CP_COMMIT();
    }

    float O[8][4] = {};
    float m_i[2] = {-1e30f, -1e30f};
    float l_i[2] = {0.f, 0.f};
    const float CSC = 0.125f * 1.4426950408889634f;  // scale * log2(e)

    for (int jj = 0; jj <= jmax; jj++){
        CP_WAIT0();
        __syncthreads();
        if (jj + 1 <= jmax){
            attn_cpa_kv(KH, KL, VT, bh_idx, jj + 1,
                        sb + AT_KV + ((jj + 1) & 1) * AKVSTG, lrowK, lqK);
            CP_COMMIT();
        }
        const uint32_t stk = sb + AT_KV + (jj & 1) * AKVSTG;

        // ---- S = Q K^T (3-term), warp covers 16 rows x 64 cols ----
        float sacc[8][4] = {};
        #pragma unroll
        for (int kc = 0; kc < 4; kc++){
            const int k0 = kc * 16;
            uint32_t qh4[4], ql4[4];
            uint32_t qa = sb + ((w * 16 + a_r) * ASA + k0 + a_c) * 2;
            ldsm4(qa, qh4);
            ldsm4(qa + AQTILE, ql4);
            #pragma unroll
            for (int p = 0; p < 4; p++){
                uint32_t ka = stk + ((p * 16 + b_r) * ASA + k0 + b_c) * 2;
                uint32_t kh4[4], kl4[4];
                ldsm4(ka, kh4);
                ldsm4(ka + AKTILE, kl4);
                mma_f16(sacc[2*p],   qh4, kh4[0], kh4[1]);
                mma_f16(sacc[2*p],   qh4, kl4[0], kl4[1]);
                mma_f16(sacc[2*p],   ql4, kh4[0], kh4[1]);
                mma_f16(sacc[2*p+1], qh4, kh4[2], kh4[3]);
                mma_f16(sacc[2*p+1], qh4, kl4[2], kl4[3]);
                mma_f16(sacc[2*p+1], ql4, kh4[2], kh4[3]);
            }
        }

        // ---- scale (+ mask on diagonal tiles), quad-local softmax ----
        const bool domask = (jj >= 2 * qt);
        #pragma unroll
        for (int hf = 0; hf < 2; hf++){
            float mx = -1e30f;
            if (domask){
                int qrow = qt * 128 + w * 16 + hf * 8 + r;
                #pragma unroll
                for (int nt = 0; nt < 8; nt++){
                    #pragma unroll
                    for (int j2 = 0; j2 < 2; j2++){
                        int col = jj * 64 + nt * 8 + c2 + j2;
                        float v = sacc[nt][hf*2+j2] * CSC;
                        if (col > qrow) v = -1e30f;
                        sacc[nt][hf*2+j2] = v;
                        mx = fmaxf(mx, v);
                    }
                }
            } else {
                #pragma unroll
                for (int nt = 0; nt < 8; nt++){
                    #pragma unroll
                    for (int j2 = 0; j2 < 2; j2++){
                        float v = sacc[nt][hf*2+j2] * CSC;
                        sacc[nt][hf*2+j2] = v;
                        mx = fmaxf(mx, v);
                    }
                }
            }
            mx = fmaxf(mx, __shfl_xor_sync(0xffffffffu, mx, 1));
            mx = fmaxf(mx, __shfl_xor_sync(0xffffffffu, mx, 2));
            float mn = fmaxf(m_i[hf], mx);
            float alpha = exp2a(m_i[hf] - mn);
            m_i[hf] = mn;
            float rs = 0.f;
            #pragma unroll
            for (int nt = 0; nt < 8; nt++){
                #pragma unroll
                for (int j2 = 0; j2 < 2; j2++){
                    float p = exp2a(sacc[nt][hf*2+j2] - mn);
                    sacc[nt][hf*2+j2] = p;
                    rs += p;
                }
            }
            rs += __shfl_xor_sync(0xffffffffu, rs, 1);
            rs += __shfl_xor_sync(0xffffffffu, rs, 2);
            l_i[hf] = l_i[hf] * alpha + rs;
            #pragma unroll
            for (int nt = 0; nt < 8; nt++){
                O[nt][hf*2]   *= alpha;
                O[nt][hf*2+1] *= alpha;
            }
        }

        // P fragments (register-only, single fp16): A-frag layout from sacc
        uint32_t pa[4][4];
        #pragma unroll
        for (int kc2 = 0; kc2 < 4; kc2++){
            pa[kc2][0] = pack2(sacc[2*kc2][0],   sacc[2*kc2][1]);
            pa[kc2][1] = pack2(sacc[2*kc2][2],   sacc[2*kc2][3]);
            pa[kc2][2] = pack2(sacc[2*kc2+1][0], sacc[2*kc2+1][1]);
            pa[kc2][3] = pack2(sacc[2*kc2+1][2], sacc[2*kc2+1][3]);
        }

        // ---- PV (1-term): full 64-kv k-dim per warp ----
        #pragma unroll
        for (int kc2 = 0; kc2 < 4; kc2++){
            #pragma unroll
            for (int p = 0; p < 4; p++){
                uint32_t va = stk + 2 * AKTILE + ((p * 16 + b_r) * ASA + kc2 * 16 + b_c) * 2;
                uint32_t vh4[4];
                ldsm4(va, vh4);
                mma_f16(O[2*p],   pa[kc2], vh4[0], vh4[1]);
                mma_f16(O[2*p+1], pa[kc2], vh4[2], vh4[3]);
            }
        }
    }

    // ---- normalize + write MH hi/lo directly (warp owns its rows) ----
    {
        uint32_t* MHH = (uint32_t*)g_MHhi4;
        uint32_t* MHL = (uint32_t*)g_MHlo4;
        #pragma unroll
        for (int hf = 0; hf < 2; hf++){
            float linv = 1.f / l_i[hf];
            int row = w * 16 + hf * 8 + r;
            size_t t = (size_t)b * SEQ + qt * 128 + row;
            #pragma unroll
            for (int nt = 0; nt < 8; nt++){
                uint32_t hi, lo;
                pack_hilo(O[nt][hf*2] * linv, O[nt][hf*2+1] * linv, hi, lo);
                size_t col = h * 64 + nt * 8 + c2;
                MHH[(t * DM + col) >> 1] = hi;
                MHL[(t * DM + col) >> 1] = lo;
            }
        }
    }
}

// ---------------------------------------------------------------------------
extern "C" void kernel_launch(void* const* d_in, const int* in_sizes, int n_in,
                              void* d_out, int out_size)
{
    const float* residual = (const float*)d_in[0];
    const float* W_Q = (const float*)d_in[1];
    const float* W_K = (const float*)d_in[2];
    const float* W_V = (const float*)d_in[3];
    const float* W_O = (const float*)d_in[4];
    float* out = (float*)d_out;

    cudaFuncSetAttribute(gemm_qkv,   cudaFuncAttributeMaxDynamicSharedMemorySize, GEMM_SMEM);
    cudaFuncSetAttribute(gemm_oproj, cudaFuncAttributeMaxDynamicSharedMemorySize, GEMM_SMEM);
    cudaFuncSetAttribute(attn_kernel, cudaFuncAttributeMaxDynamicSharedMemorySize, ATTN_SMEM);

    prep_x<<<TOK * DM / (256 * 8), 256>>>(residual);
    prep_wqkv<<<dim3(3 * NH, 12), 256>>>(W_Q, W_K, W_V);
    prep_wo<<<dim3(12, 12), 256>>>(W_O);

    gemm_qkv<<<dim3(64, 18), 256, GEMM_SMEM>>>();
    attn_kernel<<<dim3(16, BATCH * NH), 256, ATTN_SMEM>>>();
    gemm_oproj<<<dim3(64, 6), 256, 2*3*GTILE>>>(out);
}